// round 7
// baseline (speedup 1.0000x reference)
#include <cuda_runtime.h>
#include <cuda_bf16.h>
#include <cstdint>
#include <math.h>

// Problem constants
#define BTOT 32768      // BS*T = 128*256
#define SD   512        // STATE_DIM
#define EMB  32
#define HYP  256

// ---------------- global scratch (no allocations allowed) ----------------
__device__ __nv_bfloat16 g_Yh [(size_t)BTOT * SD];   // y hi (bf16)
__device__ __nv_bfloat16 g_Yl [(size_t)BTOT * SD];   // y lo (bf16)
__device__ __nv_bfloat16 g_H1h[(size_t)BTOT * HYP];
__device__ __nv_bfloat16 g_H1l[(size_t)BTOT * HYP];
__device__ __nv_bfloat16 g_HFh[(size_t)BTOT * HYP];
__device__ __nv_bfloat16 g_HFl[(size_t)BTOT * HYP];
__device__ float g_W1[(size_t)BTOT * 256];           // abs(H1@W1b+b1b)
__device__ float g_B1[(size_t)BTOT * EMB];           // y@Wb1+bb1
__device__ float g_Hv[(size_t)BTOT * EMB];           // relu(y@Wv1+bv1)
__device__ float g_WF[(size_t)BTOT * EMB];           // abs(HF@Wfb+bfb)

// transposed+split weights:  [n][k] bf16
__device__ __nv_bfloat16 g_WT0h[576 * 512];          // [W1a|Wfa|Wb1|Wv1]^T
__device__ __nv_bfloat16 g_WT0l[576 * 512];
__device__ __nv_bfloat16 g_WT1h[320 * 256];          // [W1b|Wfb|pad]^T
__device__ __nv_bfloat16 g_WT1l[320 * 256];

__device__ __forceinline__ uint32_t smem_u32(const void* p) {
    return (uint32_t)__cvta_generic_to_shared(p);
}

#define LDSM4(r0, r1, r2, r3, addr) \
    asm volatile("ldmatrix.sync.aligned.m8n8.x4.shared.b16 {%0,%1,%2,%3}, [%4];" \
        : "=r"(r0), "=r"(r1), "=r"(r2), "=r"(r3) : "r"(addr))

#define MMA_BF16(c, a, b) \
    asm volatile("mma.sync.aligned.m16n8k16.row.col.f32.bf16.bf16.f32 " \
        "{%0,%1,%2,%3}, {%4,%5,%6,%7}, {%8,%9}, {%0,%1,%2,%3};" \
        : "+f"((c)[0]), "+f"((c)[1]), "+f"((c)[2]), "+f"((c)[3]) \
        : "r"((a)[0]), "r"((a)[1]), "r"((a)[2]), "r"((a)[3]), \
          "r"((b)[0]), "r"((b)[1]))

#define CP16(dst, src) \
    asm volatile("cp.async.cg.shared.global [%0], [%1], 16;" :: "r"(dst), "l"(src))
#define CP_COMMIT() asm volatile("cp.async.commit_group;" ::: "memory")
#define CP_WAIT(n)  asm volatile("cp.async.wait_group %0;" :: "n"(n) : "memory")

__device__ __forceinline__ void bf_split(float v, __nv_bfloat16& h, __nv_bfloat16& l) {
    h = __float2bfloat16(v);
    l = __float2bfloat16(v - __bfloat162float(h));
}

// =========================================================================
// prep: transpose + hi/lo-split all GEMM weights (runs once per launch, tiny)
// =========================================================================
__global__ __launch_bounds__(256) void prep_split(
    const float* __restrict__ W1a, const float* __restrict__ Wfa,
    const float* __restrict__ Wb1, const float* __restrict__ Wv1,
    const float* __restrict__ W1b, const float* __restrict__ Wfb)
{
    int idx = blockIdx.x * 256 + threadIdx.x;
    if (idx < 576 * 512) {
        int n = idx >> 9, k = idx & 511;
        float v;
        if (n < 256)      v = W1a[k * 256 + n];
        else if (n < 512) v = Wfa[k * 256 + (n - 256)];
        else if (n < 544) v = Wb1[k * 32 + (n - 512)];
        else              v = Wv1[k * 32 + (n - 544)];
        __nv_bfloat16 h, l; bf_split(v, h, l);
        g_WT0h[idx] = h; g_WT0l[idx] = l;
    }
    int idx2 = idx - 576 * 512;
    if (idx2 >= 0 && idx2 < 320 * 256) {
        int n = idx2 >> 8, k = idx2 & 255;
        float v = 0.f;
        if (n < 256)      v = W1b[k * 256 + n];
        else if (n < 288) v = Wfb[k * 32 + (n - 256)];
        __nv_bfloat16 h, l; bf_split(v, h, l);
        g_WT1h[idx2] = h; g_WT1l[idx2] = l;
    }
}

// =========================================================================
// K1: per-row token embed; emits Y as bf16 hi/lo
// =========================================================================
__global__ __launch_bounds__(64) void k1_embed(
    const float* __restrict__ states,
    const float* __restrict__ Wt, const float* __restrict__ bt,
    const float* __restrict__ Wy, const float* __restrict__ by)
{
    __shared__ float s_sm[8 * 520];
    __shared__ float wt_sm[64 * 32];
    __shared__ float wy_sm[32 * 64];
    __shared__ float bt_sm[32];
    __shared__ float by_sm[64];

    const int tid = threadIdx.x;
    {
        const float4* Wt4 = (const float4*)Wt;
        float4* d = (float4*)wt_sm;
        for (int i = tid; i < 512; i += 64) d[i] = Wt4[i];
        const float4* Wy4 = (const float4*)Wy;
        float4* d2 = (float4*)wy_sm;
        for (int i = tid; i < 512; i += 64) d2[i] = Wy4[i];
        if (tid < 32) bt_sm[tid] = bt[tid];
        by_sm[tid] = by[tid];
    }
    {
        const float4* S4 = (const float4*)(states + (size_t)blockIdx.x * 8 * SD);
        #pragma unroll
        for (int i = 0; i < 16; i++) {
            int f4 = tid + i * 64;
            float4 v = S4[f4];
            int row = f4 >> 7;
            int e0  = (f4 & 127) * 4;
            int a   = e0 >> 6;
            int k   = e0 & 63;
            float* dp = &s_sm[row * 520 + a * 65 + k];
            dp[0] = v.x; dp[1] = v.y; dp[2] = v.z; dp[3] = v.w;
        }
    }
    __syncthreads();

    const int r = tid >> 3, a = tid & 7;
    const float* srow = &s_sm[r * 520 + a * 65];

    float e[32];
    #pragma unroll
    for (int j = 0; j < 32; j++) e[j] = bt_sm[j];
    #pragma unroll 8
    for (int k = 0; k < 64; k++) {
        float sv = srow[k];
        const float4* wrow = (const float4*)&wt_sm[k * 32];
        #pragma unroll
        for (int j4 = 0; j4 < 8; j4++) {
            float4 w = wrow[j4];
            e[j4*4+0] += sv * w.x; e[j4*4+1] += sv * w.y;
            e[j4*4+2] += sv * w.z; e[j4*4+3] += sv * w.w;
        }
    }
    #pragma unroll
    for (int j = 0; j < 32; j++) e[j] = fmaxf(e[j], 0.f);

    float y[64];
    #pragma unroll
    for (int c = 0; c < 64; c++) y[c] = by_sm[c];
    #pragma unroll 4
    for (int j = 0; j < 32; j++) {
        float ev = e[j];
        const float4* wrow = (const float4*)&wy_sm[j * 64];
        #pragma unroll
        for (int c4 = 0; c4 < 16; c4++) {
            float4 w = wrow[c4];
            y[c4*4+0] += ev * w.x; y[c4*4+1] += ev * w.y;
            y[c4*4+2] += ev * w.z; y[c4*4+3] += ev * w.w;
        }
    }
    size_t row_g = (size_t)blockIdx.x * 8 + r;
    size_t off = row_g * SD + a * 64;
    #pragma unroll
    for (int c4 = 0; c4 < 16; c4++) {
        float o0 = fmaxf(y[c4*4+0], 0.f), o1 = fmaxf(y[c4*4+1], 0.f);
        float o2 = fmaxf(y[c4*4+2], 0.f), o3 = fmaxf(y[c4*4+3], 0.f);
        __nv_bfloat16 h0,l0,h1,l1,h2,l2,h3,l3;
        bf_split(o0,h0,l0); bf_split(o1,h1,l1); bf_split(o2,h2,l2); bf_split(o3,h3,l3);
        __nv_bfloat162 hA; hA.x=h0; hA.y=h1;
        __nv_bfloat162 hB; hB.x=h2; hB.y=h3;
        __nv_bfloat162 lA; lA.x=l0; lA.y=l1;
        __nv_bfloat162 lB; lB.x=l2; lB.y=l3;
        *(__nv_bfloat162*)&g_Yh[off + c4*4]     = hA;
        *(__nv_bfloat162*)&g_Yh[off + c4*4 + 2] = hB;
        *(__nv_bfloat162*)&g_Yl[off + c4*4]     = lA;
        *(__nv_bfloat162*)&g_Yl[off + c4*4 + 2] = lB;
    }
}

// =========================================================================
// gemm_mma: bf16 mma.sync, 3-product compensation, pre-split operands.
// BM=128, BN=64, BK=32, 256 threads = 8 warps (warp tile 32x32).
// 3-stage cp.async ring, ONE __syncthreads per chunk, prefetch distance 2.
// MMA ordering: product-type outermost (hh, hl, lh) so same-acc dependent
// MMAs are 16 instructions apart (hides HMMA RAW latency).
// mode 0: C(B,576) = Y @ WT0 -> H1(h/l) | HF(h/l) | B1 | Hv
// mode 1: blocks 0-3: W1 = abs(H1@W1b+b1b); block 4: WF = abs(HF@Wfb+bfb)
// =========================================================================
#define PITCH 40
#define A_BYTES (128 * PITCH * 2)     // 10240
#define B_BYTES (64 * PITCH * 2)      // 5120
#define STAGE   (2 * A_BYTES + 2 * B_BYTES)   // 30720
#define NSTAGE  3
#define DSMEM   (NSTAGE * STAGE)              // 92160

__global__ __launch_bounds__(256, 2) void gemm_mma(
    int mode,
    const float* __restrict__ b1a, const float* __restrict__ bfa,
    const float* __restrict__ bb1, const float* __restrict__ bv1,
    const float* __restrict__ b1b, const float* __restrict__ bfb)
{
    extern __shared__ __align__(16) char dsm[];
    const uint32_t sbase = smem_u32(dsm);

    const int tid  = threadIdx.x;
    const int wid  = tid >> 5;
    const int lane = tid & 31;
    const int wm   = wid >> 1;          // 0..3 : m-quarter (32 rows)
    const int wn   = wid & 1;           // 0..1 : n-half (32 cols)
    const int nbase = blockIdx.x * 64;
    const int m0    = blockIdx.y * 128;

    const __nv_bfloat16 *Ah_p, *Al_p, *Bh_p, *Bl_p;
    int lda, ldb, NC;
    if (mode == 0) {
        Ah_p = g_Yh; Al_p = g_Yl; lda = 512;
        Bh_p = g_WT0h; Bl_p = g_WT0l; ldb = 512; NC = 16;
    } else {
        if (blockIdx.x == 4) { Ah_p = g_HFh; Al_p = g_HFl; }
        else                 { Ah_p = g_H1h; Al_p = g_H1l; }
        lda = 256;
        Bh_p = g_WT1h; Bl_p = g_WT1l; ldb = 256; NC = 8;
    }

    const int ar0 = tid >> 2, ak0 = (tid & 3) * 8;

    auto issue = [&](int c) {
        const uint32_t st = sbase + (c % NSTAGE) * STAGE;
        #pragma unroll
        for (int i = 0; i < 2; i++) {
            int row = ar0 + i * 64;
            uint32_t d = st + row * (PITCH*2) + ak0 * 2;
            const __nv_bfloat16* sh = Ah_p + (size_t)(m0 + row) * lda + c * 32 + ak0;
            const __nv_bfloat16* sl = Al_p + (size_t)(m0 + row) * lda + c * 32 + ak0;
            CP16(d, sh);
            CP16(d + A_BYTES, sl);
        }
        {
            int n = ar0;    // 0..63
            uint32_t d = st + 2 * A_BYTES + n * (PITCH*2) + ak0 * 2;
            const __nv_bfloat16* sh = Bh_p + (size_t)(nbase + n) * ldb + c * 32 + ak0;
            const __nv_bfloat16* sl = Bl_p + (size_t)(nbase + n) * ldb + c * 32 + ak0;
            CP16(d, sh);
            CP16(d + B_BYTES, sl);
        }
        CP_COMMIT();
    };

    float acc[2][4][4];
    #pragma unroll
    for (int i = 0; i < 2; i++)
        #pragma unroll
        for (int j = 0; j < 4; j++)
            #pragma unroll
            for (int q = 0; q < 4; q++) acc[i][j][q] = 0.f;

    issue(0);
    issue(1);

    const int g  = lane >> 3;
    const int li = lane & 7;

    for (int c = 0; c < NC; ++c) {
        __syncthreads();                   // all warps done computing chunk c-1
        if (c + 2 < NC) issue(c + 2);
        {
            int rem = NC - 1 - c;          // groups younger than c
            if (rem >= 2)      CP_WAIT(2);
            else if (rem == 1) CP_WAIT(1);
            else               CP_WAIT(0);
        }
        __syncthreads();                   // chunk c visible to all warps

        const uint32_t st  = sbase + (c % NSTAGE) * STAGE;
        const uint32_t sAh = st;
        const uint32_t sAl = st + A_BYTES;
        const uint32_t sBh = st + 2 * A_BYTES;
        const uint32_t sBl = st + 2 * A_BYTES + B_BYTES;

        #pragma unroll
        for (int ks = 0; ks < 2; ks++) {
            const int am = wm * 32 + (g & 1) * 8 + li;
            const int ak = (g >> 1) * 8 + ks * 16;
            const int bn = wn * 32 + (g >> 1) * 8 + li;
            const int bk = (g & 1) * 8 + ks * 16;

            uint32_t ah[2][4], al[2][4], bh[4][2], bl[4][2];
            #pragma unroll
            for (int mi = 0; mi < 2; mi++) {
                uint32_t a1 = sAh + ((am + mi * 16) * PITCH + ak) * 2;
                LDSM4(ah[mi][0], ah[mi][1], ah[mi][2], ah[mi][3], a1);
                uint32_t a2 = sAl + ((am + mi * 16) * PITCH + ak) * 2;
                LDSM4(al[mi][0], al[mi][1], al[mi][2], al[mi][3], a2);
            }
            #pragma unroll
            for (int bp = 0; bp < 2; bp++) {
                uint32_t a1 = sBh + ((bn + bp * 16) * PITCH + bk) * 2;
                LDSM4(bh[2*bp][0], bh[2*bp][1], bh[2*bp+1][0], bh[2*bp+1][1], a1);
                uint32_t a2 = sBl + ((bn + bp * 16) * PITCH + bk) * 2;
                LDSM4(bl[2*bp][0], bl[2*bp][1], bl[2*bp+1][0], bl[2*bp+1][1], a2);
            }
            // product-type outermost: same-acc MMAs are 16 apart
            #pragma unroll
            for (int mi = 0; mi < 2; mi++)
                #pragma unroll
                for (int ni = 0; ni < 4; ni++)
                    MMA_BF16(acc[mi][ni], ah[mi], bh[ni]);
            #pragma unroll
            for (int mi = 0; mi < 2; mi++)
                #pragma unroll
                for (int ni = 0; ni < 4; ni++)
                    MMA_BF16(acc[mi][ni], ah[mi], bl[ni]);
            #pragma unroll
            for (int mi = 0; mi < 2; mi++)
                #pragma unroll
                for (int ni = 0; ni < 4; ni++)
                    MMA_BF16(acc[mi][ni], al[mi], bh[ni]);
        }
    }

    // ---- epilogue ----
    #pragma unroll
    for (int mi = 0; mi < 2; mi++) {
        #pragma unroll
        for (int ni = 0; ni < 4; ni++) {
            int m  = m0 + wm * 32 + mi * 16 + (lane >> 2);
            int ng = nbase + wn * 32 + ni * 8 + 2 * (lane & 3);
            #pragma unroll
            for (int half = 0; half < 2; half++) {
                int mm = m + half * 8;
                float x0 = acc[mi][ni][half * 2 + 0];
                float x1 = acc[mi][ni][half * 2 + 1];
                if (mode == 0) {
                    if (ng < 256) {
                        float2 b = *(const float2*)&b1a[ng];
                        float o0 = fmaxf(x0 + b.x, 0.f), o1 = fmaxf(x1 + b.y, 0.f);
                        __nv_bfloat16 h0,l0,h1,l1;
                        bf_split(o0,h0,l0); bf_split(o1,h1,l1);
                        __nv_bfloat162 hv; hv.x=h0; hv.y=h1;
                        __nv_bfloat162 lv; lv.x=l0; lv.y=l1;
                        *(__nv_bfloat162*)&g_H1h[(size_t)mm * 256 + ng] = hv;
                        *(__nv_bfloat162*)&g_H1l[(size_t)mm * 256 + ng] = lv;
                    } else if (ng < 512) {
                        int nl = ng - 256;
                        float2 b = *(const float2*)&bfa[nl];
                        float o0 = fmaxf(x0 + b.x, 0.f), o1 = fmaxf(x1 + b.y, 0.f);
                        __nv_bfloat16 h0,l0,h1,l1;
                        bf_split(o0,h0,l0); bf_split(o1,h1,l1);
                        __nv_bfloat162 hv; hv.x=h0; hv.y=h1;
                        __nv_bfloat162 lv; lv.x=l0; lv.y=l1;
                        *(__nv_bfloat162*)&g_HFh[(size_t)mm * 256 + nl] = hv;
                        *(__nv_bfloat162*)&g_HFl[(size_t)mm * 256 + nl] = lv;
                    } else if (ng < 544) {
                        int nl = ng - 512;
                        float2 b = *(const float2*)&bb1[nl];
                        float2 o = make_float2(x0 + b.x, x1 + b.y);
                        *(float2*)&g_B1[(size_t)mm * 32 + nl] = o;
                    } else {
                        int nl = ng - 544;
                        float2 b = *(const float2*)&bv1[nl];
                        float2 o = make_float2(fmaxf(x0 + b.x, 0.f), fmaxf(x1 + b.y, 0.f));
                        *(float2*)&g_Hv[(size_t)mm * 32 + nl] = o;
                    }
                } else {
                    if (nbase < 256) {
                        float2 b = *(const float2*)&b1b[ng];
                        float2 o = make_float2(fabsf(x0 + b.x), fabsf(x1 + b.y));
                        *(float2*)&g_W1[(size_t)mm * 256 + ng] = o;
                    } else {
                        int nl = ng - 256;
                        if (nl < 32) {
                            float2 b = *(const float2*)&bfb[nl];
                            float2 o = make_float2(fabsf(x0 + b.x), fabsf(x1 + b.y));
                            *(float2*)&g_WF[(size_t)mm * 32 + nl] = o;
                        }
                    }
                }
            }
        }
    }
}

// =========================================================================
// K4: final fused epilogue. One warp per row; lane = EMB index e.
// =========================================================================
__device__ __forceinline__ float wred(float v) {
    #pragma unroll
    for (int o = 16; o > 0; o >>= 1) v += __shfl_xor_sync(0xFFFFFFFFu, v, o);
    return v;
}

__global__ __launch_bounds__(256) void k4_final(
    const float* __restrict__ agent_qs,
    const float* __restrict__ Wv2, const float* __restrict__ bv2,
    float* __restrict__ out)
{
    const int w = threadIdx.x >> 5, lane = threadIdx.x & 31;
    const size_t r = (size_t)blockIdx.x * 8 + w;

    const float wv2v = Wv2[lane];

    float q[8];
    #pragma unroll
    for (int a = 0; a < 8; a++) q[a] = agent_qs[r * 8 + a];

    float w1r[8];
    const float* w1p = g_W1 + r * 256;
    #pragma unroll
    for (int a = 0; a < 8; a++) w1r[a] = w1p[a * 32 + lane];

    float x = g_B1[r * 32 + lane];
    #pragma unroll
    for (int a = 0; a < 8; a++) x += q[a] * w1r[a];
    const float h    = (x > 0.f) ? x : expm1f(x);
    const float delu = (h < 0.f) ? expf(h) : 1.f;

    const float wf = g_WF[r * 32 + lane];
    const float hv = g_Hv[r * 32 + lane];

    const float vsum = wred(hv * wv2v);
    const float qt   = wred(h * wf);
    if (lane == 0) out[r] = qt + vsum + bv2[0];

    const float t = delu * wf;
    float* gout = out + BTOT;
    #pragma unroll
    for (int a = 0; a < 8; a++) {
        float s = wred(w1r[a] * t);
        if (lane == a) gout[r * 8 + a] = s;
    }
}

// =========================================================================
extern "C" void kernel_launch(void* const* d_in, const int* in_sizes, int n_in,
                              void* d_out, int out_size)
{
    (void)in_sizes; (void)n_in; (void)out_size;
    const float* agent_qs = (const float*)d_in[0];
    const float* states = (const float*)d_in[2];   // d_in[1]=hist, d_in[3]=obs unused
    const float* W_tok  = (const float*)d_in[4];
    const float* b_tok  = (const float*)d_in[5];
    const float* W_yfc  = (const float*)d_in[6];
    const float* b_yfc  = (const float*)d_in[7];
    const float* W1a    = (const float*)d_in[8];
    const float* b1a    = (const float*)d_in[9];
    const float* W1b    = (const float*)d_in[10];
    const float* b1b    = (const float*)d_in[11];
    const float* Wfa    = (const float*)d_in[12];
    const float* bfa    = (const float*)d_in[13];
    const float* Wfb    = (const float*)d_in[14];
    const float* bfb    = (const float*)d_in[15];
    const float* Wb1    = (const float*)d_in[16];
    const float* bb1    = (const float*)d_in[17];
    const float* Wv1    = (const float*)d_in[18];
    const float* bv1    = (const float*)d_in[19];
    const float* Wv2    = (const float*)d_in[20];
    const float* bv2    = (const float*)d_in[21];
    float* out = (float*)d_out;

    cudaFuncSetAttribute(gemm_mma, cudaFuncAttributeMaxDynamicSharedMemorySize, DSMEM);

    prep_split<<<1472, 256>>>(W1a, Wfa, Wb1, Wv1, W1b, Wfb);
    k1_embed<<<BTOT / 8, 64>>>(states, W_tok, b_tok, W_yfc, b_yfc);
    gemm_mma<<<dim3(9, BTOT / 128), 256, DSMEM>>>(0, b1a, bfa, bb1, bv1, b1b, bfb);
    gemm_mma<<<dim3(5, BTOT / 128), 256, DSMEM>>>(1, b1a, bfa, bb1, bv1, b1b, bfb);
    k4_final<<<BTOT / 8, 256>>>(agent_qs, Wv2, bv2, out);
}

// round 8
// speedup vs baseline: 1.4436x; 1.4436x over previous
#include <cuda_runtime.h>
#include <cuda_bf16.h>
#include <cstdint>
#include <math.h>

// Problem constants
#define BTOT 32768      // BS*T = 128*256
#define SD   512        // STATE_DIM
#define EMB  32
#define HYP  256

// ---------------- global scratch (no allocations allowed) ----------------
__device__ __nv_bfloat16 g_Yh [(size_t)BTOT * SD];   // y hi (bf16)
__device__ __nv_bfloat16 g_Yl [(size_t)BTOT * SD];   // y lo (bf16)
__device__ __nv_bfloat16 g_H1h[(size_t)BTOT * HYP];
__device__ __nv_bfloat16 g_H1l[(size_t)BTOT * HYP];
__device__ __nv_bfloat16 g_HFh[(size_t)BTOT * HYP];
__device__ __nv_bfloat16 g_HFl[(size_t)BTOT * HYP];
__device__ float g_W1[(size_t)BTOT * 256];           // abs(H1@W1b+b1b)
__device__ float g_B1[(size_t)BTOT * EMB];           // y@Wb1+bb1
__device__ float g_Hv[(size_t)BTOT * EMB];           // relu(y@Wv1+bv1)
__device__ float g_WF[(size_t)BTOT * EMB];           // abs(HF@Wfb+bfb)

// transposed+split weights:  [n][k] bf16
__device__ __nv_bfloat16 g_WT0h[576 * 512];          // [W1a|Wfa|Wb1|Wv1]^T
__device__ __nv_bfloat16 g_WT0l[576 * 512];
__device__ __nv_bfloat16 g_WT1h[320 * 256];          // [W1b|Wfb|pad]^T
__device__ __nv_bfloat16 g_WT1l[320 * 256];

__device__ __forceinline__ uint32_t smem_u32(const void* p) {
    return (uint32_t)__cvta_generic_to_shared(p);
}

#define LDSM4(r0, r1, r2, r3, addr) \
    asm volatile("ldmatrix.sync.aligned.m8n8.x4.shared.b16 {%0,%1,%2,%3}, [%4];" \
        : "=r"(r0), "=r"(r1), "=r"(r2), "=r"(r3) : "r"(addr))

#define MMA_BF16(c, a, b) \
    asm volatile("mma.sync.aligned.m16n8k16.row.col.f32.bf16.bf16.f32 " \
        "{%0,%1,%2,%3}, {%4,%5,%6,%7}, {%8,%9}, {%0,%1,%2,%3};" \
        : "+f"((c)[0]), "+f"((c)[1]), "+f"((c)[2]), "+f"((c)[3]) \
        : "r"((a)[0]), "r"((a)[1]), "r"((a)[2]), "r"((a)[3]), \
          "r"((b)[0]), "r"((b)[1]))

#define CP16(dst, src) \
    asm volatile("cp.async.cg.shared.global [%0], [%1], 16;" :: "r"(dst), "l"(src))
#define CP_COMMIT() asm volatile("cp.async.commit_group;" ::: "memory")
#define CP_WAIT(n)  asm volatile("cp.async.wait_group %0;" :: "n"(n) : "memory")

__device__ __forceinline__ void bf_split(float v, __nv_bfloat16& h, __nv_bfloat16& l) {
    h = __float2bfloat16(v);
    l = __float2bfloat16(v - __bfloat162float(h));
}

// =========================================================================
// prep: transpose + hi/lo-split all GEMM weights (runs once per launch, tiny)
// =========================================================================
__global__ __launch_bounds__(256) void prep_split(
    const float* __restrict__ W1a, const float* __restrict__ Wfa,
    const float* __restrict__ Wb1, const float* __restrict__ Wv1,
    const float* __restrict__ W1b, const float* __restrict__ Wfb)
{
    int idx = blockIdx.x * 256 + threadIdx.x;
    if (idx < 576 * 512) {
        int n = idx >> 9, k = idx & 511;
        float v;
        if (n < 256)      v = W1a[k * 256 + n];
        else if (n < 512) v = Wfa[k * 256 + (n - 256)];
        else if (n < 544) v = Wb1[k * 32 + (n - 512)];
        else              v = Wv1[k * 32 + (n - 544)];
        __nv_bfloat16 h, l; bf_split(v, h, l);
        g_WT0h[idx] = h; g_WT0l[idx] = l;
    }
    int idx2 = idx - 576 * 512;
    if (idx2 >= 0 && idx2 < 320 * 256) {
        int n = idx2 >> 8, k = idx2 & 255;
        float v = 0.f;
        if (n < 256)      v = W1b[k * 256 + n];
        else if (n < 288) v = Wfb[k * 32 + (n - 256)];
        __nv_bfloat16 h, l; bf_split(v, h, l);
        g_WT1h[idx2] = h; g_WT1l[idx2] = l;
    }
}

// =========================================================================
// k1_mma: token embed on tensor cores.
// A = states viewed as (B*8 = 262144, 64) row-major (contiguous).
// stage1: E = relu(A @ W_tok + b_tok)   (K=64, N=32)
// stage2: Y = relu(E @ W_yfc + b_yfc)   (K=32, N=64) -> g_Yh/g_Yl
//   (Y row R=b*8+a maps to g_Y[b][a*64+c] = linear R*64+c, i.e. contiguous)
// 128 rows/CTA, 8 warps, each warp owns 16 rows. bf16 3-product everywhere.
// =========================================================================
#define P_A 72     // pitch for k=64 tiles (144B rows: conflict-free ldmatrix)
#define P_E 40     // pitch for k=32 tiles

// dynamic smem layout (bytes)
#define K1_sAh  0
#define K1_sAl  (K1_sAh + 128 * P_A * 2)      // 18432
#define K1_sBh  (K1_sAl + 128 * P_A * 2)      // 36864  (Wtok^T [32][72])
#define K1_sBl  (K1_sBh + 32 * P_A * 2)       // 41472
#define K1_sEh  (K1_sBl + 32 * P_A * 2)       // 46080  (E [128][40])
#define K1_sEl  (K1_sEh + 128 * P_E * 2)      // 56320
#define K1_sCh  (K1_sEl + 128 * P_E * 2)      // 66560  (Wyfc^T [64][40])
#define K1_sCl  (K1_sCh + 64 * P_E * 2)       // 71680
#define K1_SMEM (K1_sCl + 64 * P_E * 2)       // 76800

__global__ __launch_bounds__(256, 2) void k1_mma(
    const float* __restrict__ states,
    const float* __restrict__ Wt, const float* __restrict__ bt,
    const float* __restrict__ Wy, const float* __restrict__ by)
{
    extern __shared__ __align__(16) char dsm[];
    const uint32_t sb = smem_u32(dsm);
    const int tid  = threadIdx.x;
    const int w    = tid >> 5;
    const int lane = tid & 31;
    const int g    = lane >> 3;
    const int li   = lane & 7;

    // ---- stage A: 128 rows x 64 k fp32 -> hi/lo bf16 ----
    {
        const float4* S4 = (const float4*)(states + (size_t)blockIdx.x * 128 * 64);
        __nv_bfloat16* Ah = (__nv_bfloat16*)(dsm + K1_sAh);
        __nv_bfloat16* Al = (__nv_bfloat16*)(dsm + K1_sAl);
        #pragma unroll
        for (int i = 0; i < 8; i++) {
            int idx = tid + i * 256;          // 0..2047 float4
            int row = idx >> 4;
            int k4  = (idx & 15) * 4;
            float4 v = S4[idx];
            int e = row * P_A + k4;
            __nv_bfloat16 h0,l0,h1,l1,h2,l2,h3,l3;
            bf_split(v.x,h0,l0); bf_split(v.y,h1,l1);
            bf_split(v.z,h2,l2); bf_split(v.w,h3,l3);
            __nv_bfloat162 ha; ha.x=h0; ha.y=h1;
            __nv_bfloat162 hb; hb.x=h2; hb.y=h3;
            __nv_bfloat162 la; la.x=l0; la.y=l1;
            __nv_bfloat162 lb; lb.x=l2; lb.y=l3;
            *(__nv_bfloat162*)&Ah[e]   = ha;  *(__nv_bfloat162*)&Ah[e+2] = hb;
            *(__nv_bfloat162*)&Al[e]   = la;  *(__nv_bfloat162*)&Al[e+2] = lb;
        }
        // Wtok^T [n=32][k=64]
        __nv_bfloat16* Bh = (__nv_bfloat16*)(dsm + K1_sBh);
        __nv_bfloat16* Bl = (__nv_bfloat16*)(dsm + K1_sBl);
        #pragma unroll
        for (int i = 0; i < 8; i++) {
            int idx = tid + i * 256;          // 0..2047
            int n = idx & 31, k = idx >> 5;
            __nv_bfloat16 h, l; bf_split(Wt[k * 32 + n], h, l);
            Bh[n * P_A + k] = h; Bl[n * P_A + k] = l;
        }
        // Wyfc^T [n=64][k=32]
        __nv_bfloat16* Ch = (__nv_bfloat16*)(dsm + K1_sCh);
        __nv_bfloat16* Cl = (__nv_bfloat16*)(dsm + K1_sCl);
        #pragma unroll
        for (int i = 0; i < 8; i++) {
            int idx = tid + i * 256;
            int n = idx & 63, k = idx >> 6;
            __nv_bfloat16 h, l; bf_split(Wy[k * 64 + n], h, l);
            Ch[n * P_E + k] = h; Cl[n * P_E + k] = l;
        }
    }
    __syncthreads();

    // ---- stage1: E = relu(A @ Wtok + bt),  per warp 16 rows ----
    {
        float acc[4][4];
        #pragma unroll
        for (int i = 0; i < 4; i++)
            #pragma unroll
            for (int q = 0; q < 4; q++) acc[i][q] = 0.f;

        #pragma unroll
        for (int ks = 0; ks < 4; ks++) {
            const int am = w * 16 + (g & 1) * 8 + li;
            const int ak = (g >> 1) * 8 + ks * 16;
            const int bn = (g >> 1) * 8 + li;
            const int bk = (g & 1) * 8 + ks * 16;
            uint32_t ah[4], al[4], bh[4][2], bl[4][2];
            LDSM4(ah[0],ah[1],ah[2],ah[3], sb + K1_sAh + (am * P_A + ak) * 2);
            LDSM4(al[0],al[1],al[2],al[3], sb + K1_sAl + (am * P_A + ak) * 2);
            #pragma unroll
            for (int bp = 0; bp < 2; bp++) {
                LDSM4(bh[2*bp][0], bh[2*bp][1], bh[2*bp+1][0], bh[2*bp+1][1],
                      sb + K1_sBh + ((bn + bp * 16) * P_A + bk) * 2);
                LDSM4(bl[2*bp][0], bl[2*bp][1], bl[2*bp+1][0], bl[2*bp+1][1],
                      sb + K1_sBl + ((bn + bp * 16) * P_A + bk) * 2);
            }
            #pragma unroll
            for (int ni = 0; ni < 4; ni++) {
                MMA_BF16(acc[ni], ah, bh[ni]);
                MMA_BF16(acc[ni], ah, bl[ni]);
                MMA_BF16(acc[ni], al, bh[ni]);
            }
        }
        // epilogue1: relu + bias, split into sE
        __nv_bfloat16* Eh = (__nv_bfloat16*)(dsm + K1_sEh);
        __nv_bfloat16* El = (__nv_bfloat16*)(dsm + K1_sEl);
        #pragma unroll
        for (int ni = 0; ni < 4; ni++) {
            int n = ni * 8 + 2 * (lane & 3);
            float b0 = bt[n], b1 = bt[n + 1];
            #pragma unroll
            for (int half = 0; half < 2; half++) {
                int m = w * 16 + (lane >> 2) + half * 8;
                float o0 = fmaxf(acc[ni][half*2+0] + b0, 0.f);
                float o1 = fmaxf(acc[ni][half*2+1] + b1, 0.f);
                __nv_bfloat16 h0,l0,h1,l1;
                bf_split(o0,h0,l0); bf_split(o1,h1,l1);
                __nv_bfloat162 hv; hv.x=h0; hv.y=h1;
                __nv_bfloat162 lv; lv.x=l0; lv.y=l1;
                *(__nv_bfloat162*)&Eh[m * P_E + n] = hv;
                *(__nv_bfloat162*)&El[m * P_E + n] = lv;
            }
        }
    }
    __syncthreads();

    // ---- stage2: Y = relu(E @ Wyfc + by),  per warp 16 rows, N=64 ----
    {
        float acc[8][4];
        #pragma unroll
        for (int i = 0; i < 8; i++)
            #pragma unroll
            for (int q = 0; q < 4; q++) acc[i][q] = 0.f;

        #pragma unroll
        for (int ks = 0; ks < 2; ks++) {
            const int am = w * 16 + (g & 1) * 8 + li;
            const int ak = (g >> 1) * 8 + ks * 16;
            const int bn = (g >> 1) * 8 + li;
            const int bk = (g & 1) * 8 + ks * 16;
            uint32_t ah[4], al[4], bh[8][2], bl[8][2];
            LDSM4(ah[0],ah[1],ah[2],ah[3], sb + K1_sEh + (am * P_E + ak) * 2);
            LDSM4(al[0],al[1],al[2],al[3], sb + K1_sEl + (am * P_E + ak) * 2);
            #pragma unroll
            for (int bp = 0; bp < 4; bp++) {
                LDSM4(bh[2*bp][0], bh[2*bp][1], bh[2*bp+1][0], bh[2*bp+1][1],
                      sb + K1_sCh + ((bn + bp * 16) * P_E + bk) * 2);
                LDSM4(bl[2*bp][0], bl[2*bp][1], bl[2*bp+1][0], bl[2*bp+1][1],
                      sb + K1_sCl + ((bn + bp * 16) * P_E + bk) * 2);
            }
            #pragma unroll
            for (int ni = 0; ni < 8; ni++) {
                MMA_BF16(acc[ni], ah, bh[ni]);
                MMA_BF16(acc[ni], ah, bl[ni]);
                MMA_BF16(acc[ni], al, bh[ni]);
            }
        }
        // epilogue2: relu + bias, split, write g_Yh/g_Yl (linear R*64+n)
        #pragma unroll
        for (int ni = 0; ni < 8; ni++) {
            int n = ni * 8 + 2 * (lane & 3);
            float b0 = by[n], b1 = by[n + 1];
            #pragma unroll
            for (int half = 0; half < 2; half++) {
                int m = w * 16 + (lane >> 2) + half * 8;
                size_t R = (size_t)blockIdx.x * 128 + m;
                float o0 = fmaxf(acc[ni][half*2+0] + b0, 0.f);
                float o1 = fmaxf(acc[ni][half*2+1] + b1, 0.f);
                __nv_bfloat16 h0,l0,h1,l1;
                bf_split(o0,h0,l0); bf_split(o1,h1,l1);
                __nv_bfloat162 hv; hv.x=h0; hv.y=h1;
                __nv_bfloat162 lv; lv.x=l0; lv.y=l1;
                *(__nv_bfloat162*)&g_Yh[R * 64 + n] = hv;
                *(__nv_bfloat162*)&g_Yl[R * 64 + n] = lv;
            }
        }
    }
}

// =========================================================================
// gemm_mma: bf16 mma.sync, 3-product compensation, pre-split operands.
// (exact R5 configuration: BM=128, BN=64, BK=32, 8 warps, warp tile 32x32,
//  2-stage cp.async double buffer)
// mode 0: C(B,576) = Y @ WT0 -> H1(h/l) | HF(h/l) | B1 | Hv
// mode 1: blocks 0-3: W1 = abs(H1@W1b+b1b); block 4: WF = abs(HF@Wfb+bfb)
// =========================================================================
#define PITCH 40
#define A_BYTES (128 * PITCH * 2)     // 10240
#define B_BYTES (64 * PITCH * 2)      // 5120
#define STAGE   (2 * A_BYTES + 2 * B_BYTES)   // 30720
#define DSMEM   (2 * STAGE)                   // 61440

__global__ __launch_bounds__(256) void gemm_mma(
    int mode,
    const float* __restrict__ b1a, const float* __restrict__ bfa,
    const float* __restrict__ bb1, const float* __restrict__ bv1,
    const float* __restrict__ b1b, const float* __restrict__ bfb)
{
    extern __shared__ __align__(16) char dsm[];
    const uint32_t sbase = smem_u32(dsm);

    const int tid  = threadIdx.x;
    const int wid  = tid >> 5;
    const int lane = tid & 31;
    const int wm   = wid >> 1;          // 0..3 : m-quarter (32 rows)
    const int wn   = wid & 1;           // 0..1 : n-half (32 cols)
    const int nbase = blockIdx.x * 64;
    const int m0    = blockIdx.y * 128;

    const __nv_bfloat16 *Ah_p, *Al_p, *Bh_p, *Bl_p;
    int lda, ldb, NC;
    if (mode == 0) {
        Ah_p = g_Yh; Al_p = g_Yl; lda = 512;
        Bh_p = g_WT0h; Bl_p = g_WT0l; ldb = 512; NC = 16;
    } else {
        if (blockIdx.x == 4) { Ah_p = g_HFh; Al_p = g_HFl; }
        else                 { Ah_p = g_H1h; Al_p = g_H1l; }
        lda = 256;
        Bh_p = g_WT1h; Bl_p = g_WT1l; ldb = 256; NC = 8;
    }

    const int ar0 = tid >> 2,  ak0 = (tid & 3) * 8;

    auto issue = [&](int c) {
        const uint32_t st = sbase + (c & 1) * STAGE;
        #pragma unroll
        for (int i = 0; i < 2; i++) {
            int row = ar0 + i * 64;
            uint32_t d = st + row * (PITCH*2) + ak0 * 2;
            const __nv_bfloat16* sh = Ah_p + (size_t)(m0 + row) * lda + c * 32 + ak0;
            const __nv_bfloat16* sl = Al_p + (size_t)(m0 + row) * lda + c * 32 + ak0;
            CP16(d, sh);
            CP16(d + A_BYTES, sl);
        }
        {
            int n  = ar0;
            uint32_t d = st + 2 * A_BYTES + n * (PITCH*2) + ak0 * 2;
            const __nv_bfloat16* sh = Bh_p + (size_t)(nbase + n) * ldb + c * 32 + ak0;
            const __nv_bfloat16* sl = Bl_p + (size_t)(nbase + n) * ldb + c * 32 + ak0;
            CP16(d, sh);
            CP16(d + B_BYTES, sl);
        }
        CP_COMMIT();
    };

    float acc[2][4][4];
    #pragma unroll
    for (int i = 0; i < 2; i++)
        #pragma unroll
        for (int j = 0; j < 4; j++)
            #pragma unroll
            for (int q = 0; q < 4; q++) acc[i][j][q] = 0.f;

    issue(0);

    const int g  = lane >> 3;
    const int li = lane & 7;

    for (int c = 0; c < NC; ++c) {
        if (c + 1 < NC) { issue(c + 1); CP_WAIT(1); }
        else            { CP_WAIT(0); }
        __syncthreads();

        const uint32_t st = sbase + (c & 1) * STAGE;
        const uint32_t sAh = st;
        const uint32_t sAl = st + A_BYTES;
        const uint32_t sBh = st + 2 * A_BYTES;
        const uint32_t sBl = st + 2 * A_BYTES + B_BYTES;

        #pragma unroll
        for (int ks = 0; ks < 2; ks++) {
            const int am = wm * 32 + (g & 1) * 8 + li;
            const int ak = (g >> 1) * 8 + ks * 16;
            const int bn = wn * 32 + (g >> 1) * 8 + li;
            const int bk = (g & 1) * 8 + ks * 16;

            uint32_t ah[2][4], al[2][4], bh[4][2], bl[4][2];
            #pragma unroll
            for (int mi = 0; mi < 2; mi++) {
                uint32_t a1 = sAh + ((am + mi * 16) * PITCH + ak) * 2;
                LDSM4(ah[mi][0], ah[mi][1], ah[mi][2], ah[mi][3], a1);
                uint32_t a2 = sAl + ((am + mi * 16) * PITCH + ak) * 2;
                LDSM4(al[mi][0], al[mi][1], al[mi][2], al[mi][3], a2);
            }
            #pragma unroll
            for (int bp = 0; bp < 2; bp++) {
                uint32_t a1 = sBh + ((bn + bp * 16) * PITCH + bk) * 2;
                LDSM4(bh[2*bp][0], bh[2*bp][1], bh[2*bp+1][0], bh[2*bp+1][1], a1);
                uint32_t a2 = sBl + ((bn + bp * 16) * PITCH + bk) * 2;
                LDSM4(bl[2*bp][0], bl[2*bp][1], bl[2*bp+1][0], bl[2*bp+1][1], a2);
            }
            #pragma unroll
            for (int mi = 0; mi < 2; mi++)
                #pragma unroll
                for (int ni = 0; ni < 4; ni++) {
                    MMA_BF16(acc[mi][ni], ah[mi], bh[ni]);
                    MMA_BF16(acc[mi][ni], ah[mi], bl[ni]);
                    MMA_BF16(acc[mi][ni], al[mi], bh[ni]);
                }
        }
        __syncthreads();
    }

    // ---- epilogue ----
    #pragma unroll
    for (int mi = 0; mi < 2; mi++) {
        #pragma unroll
        for (int ni = 0; ni < 4; ni++) {
            int m  = m0 + wm * 32 + mi * 16 + (lane >> 2);
            int ng = nbase + wn * 32 + ni * 8 + 2 * (lane & 3);
            #pragma unroll
            for (int half = 0; half < 2; half++) {
                int mm = m + half * 8;
                float x0 = acc[mi][ni][half * 2 + 0];
                float x1 = acc[mi][ni][half * 2 + 1];
                if (mode == 0) {
                    if (ng < 256) {
                        float2 b = *(const float2*)&b1a[ng];
                        float o0 = fmaxf(x0 + b.x, 0.f), o1 = fmaxf(x1 + b.y, 0.f);
                        __nv_bfloat16 h0,l0,h1,l1;
                        bf_split(o0,h0,l0); bf_split(o1,h1,l1);
                        __nv_bfloat162 hv; hv.x=h0; hv.y=h1;
                        __nv_bfloat162 lv; lv.x=l0; lv.y=l1;
                        *(__nv_bfloat162*)&g_H1h[(size_t)mm * 256 + ng] = hv;
                        *(__nv_bfloat162*)&g_H1l[(size_t)mm * 256 + ng] = lv;
                    } else if (ng < 512) {
                        int nl = ng - 256;
                        float2 b = *(const float2*)&bfa[nl];
                        float o0 = fmaxf(x0 + b.x, 0.f), o1 = fmaxf(x1 + b.y, 0.f);
                        __nv_bfloat16 h0,l0,h1,l1;
                        bf_split(o0,h0,l0); bf_split(o1,h1,l1);
                        __nv_bfloat162 hv; hv.x=h0; hv.y=h1;
                        __nv_bfloat162 lv; lv.x=l0; lv.y=l1;
                        *(__nv_bfloat162*)&g_HFh[(size_t)mm * 256 + nl] = hv;
                        *(__nv_bfloat162*)&g_HFl[(size_t)mm * 256 + nl] = lv;
                    } else if (ng < 544) {
                        int nl = ng - 512;
                        float2 b = *(const float2*)&bb1[nl];
                        float2 o = make_float2(x0 + b.x, x1 + b.y);
                        *(float2*)&g_B1[(size_t)mm * 32 + nl] = o;
                    } else {
                        int nl = ng - 544;
                        float2 b = *(const float2*)&bv1[nl];
                        float2 o = make_float2(fmaxf(x0 + b.x, 0.f), fmaxf(x1 + b.y, 0.f));
                        *(float2*)&g_Hv[(size_t)mm * 32 + nl] = o;
                    }
                } else {
                    if (nbase < 256) {
                        float2 b = *(const float2*)&b1b[ng];
                        float2 o = make_float2(fabsf(x0 + b.x), fabsf(x1 + b.y));
                        *(float2*)&g_W1[(size_t)mm * 256 + ng] = o;
                    } else {
                        int nl = ng - 256;
                        if (nl < 32) {
                            float2 b = *(const float2*)&bfb[nl];
                            float2 o = make_float2(fabsf(x0 + b.x), fabsf(x1 + b.y));
                            *(float2*)&g_WF[(size_t)mm * 32 + nl] = o;
                        }
                    }
                }
            }
        }
    }
}

// =========================================================================
// K4: final fused epilogue. One warp per row; lane = EMB index e.
// =========================================================================
__device__ __forceinline__ float wred(float v) {
    #pragma unroll
    for (int o = 16; o > 0; o >>= 1) v += __shfl_xor_sync(0xFFFFFFFFu, v, o);
    return v;
}

__global__ __launch_bounds__(256) void k4_final(
    const float* __restrict__ agent_qs,
    const float* __restrict__ Wv2, const float* __restrict__ bv2,
    float* __restrict__ out)
{
    const int w = threadIdx.x >> 5, lane = threadIdx.x & 31;
    const size_t r = (size_t)blockIdx.x * 8 + w;

    const float wv2v = Wv2[lane];

    float q[8];
    #pragma unroll
    for (int a = 0; a < 8; a++) q[a] = agent_qs[r * 8 + a];

    float w1r[8];
    const float* w1p = g_W1 + r * 256;
    #pragma unroll
    for (int a = 0; a < 8; a++) w1r[a] = w1p[a * 32 + lane];

    float x = g_B1[r * 32 + lane];
    #pragma unroll
    for (int a = 0; a < 8; a++) x += q[a] * w1r[a];
    const float h    = (x > 0.f) ? x : expm1f(x);
    const float delu = (h < 0.f) ? expf(h) : 1.f;

    const float wf = g_WF[r * 32 + lane];
    const float hv = g_Hv[r * 32 + lane];

    const float vsum = wred(hv * wv2v);
    const float qt   = wred(h * wf);
    if (lane == 0) out[r] = qt + vsum + bv2[0];

    const float t = delu * wf;
    float* gout = out + BTOT;
    #pragma unroll
    for (int a = 0; a < 8; a++) {
        float s = wred(w1r[a] * t);
        if (lane == a) gout[r * 8 + a] = s;
    }
}

// =========================================================================
extern "C" void kernel_launch(void* const* d_in, const int* in_sizes, int n_in,
                              void* d_out, int out_size)
{
    (void)in_sizes; (void)n_in; (void)out_size;
    const float* agent_qs = (const float*)d_in[0];
    const float* states = (const float*)d_in[2];   // d_in[1]=hist, d_in[3]=obs unused
    const float* W_tok  = (const float*)d_in[4];
    const float* b_tok  = (const float*)d_in[5];
    const float* W_yfc  = (const float*)d_in[6];
    const float* b_yfc  = (const float*)d_in[7];
    const float* W1a    = (const float*)d_in[8];
    const float* b1a    = (const float*)d_in[9];
    const float* W1b    = (const float*)d_in[10];
    const float* b1b    = (const float*)d_in[11];
    const float* Wfa    = (const float*)d_in[12];
    const float* bfa    = (const float*)d_in[13];
    const float* Wfb    = (const float*)d_in[14];
    const float* bfb    = (const float*)d_in[15];
    const float* Wb1    = (const float*)d_in[16];
    const float* bb1    = (const float*)d_in[17];
    const float* Wv1    = (const float*)d_in[18];
    const float* bv1    = (const float*)d_in[19];
    const float* Wv2    = (const float*)d_in[20];
    const float* bv2    = (const float*)d_in[21];
    float* out = (float*)d_out;

    cudaFuncSetAttribute(gemm_mma, cudaFuncAttributeMaxDynamicSharedMemorySize, DSMEM);
    cudaFuncSetAttribute(k1_mma, cudaFuncAttributeMaxDynamicSharedMemorySize, K1_SMEM);

    prep_split<<<1472, 256>>>(W1a, Wfa, Wb1, Wv1, W1b, Wfb);
    k1_mma<<<2048, 256, K1_SMEM>>>(states, W_tok, b_tok, W_yfc, b_yfc);
    gemm_mma<<<dim3(9, BTOT / 128), 256, DSMEM>>>(0, b1a, bfa, bb1, bv1, b1b, bfb);
    gemm_mma<<<dim3(5, BTOT / 128), 256, DSMEM>>>(1, b1a, bfa, bb1, bv1, b1b, bfb);
    k4_final<<<BTOT / 8, 256>>>(agent_qs, Wv2, bv2, out);
}

// round 9
// speedup vs baseline: 1.7775x; 1.2313x over previous
#include <cuda_runtime.h>
#include <cuda_fp16.h>
#include <cstdint>
#include <math.h>

// Problem constants
#define BTOT 32768      // BS*T = 128*256
#define SD   512        // STATE_DIM
#define EMB  32
#define HYP  256

// ---------------- global scratch (no allocations allowed) ----------------
// A-side tensors: fp16 hi/lo (22-bit effective mantissa)
__device__ __half g_Yh [(size_t)BTOT * SD];
__device__ __half g_Yl [(size_t)BTOT * SD];
__device__ __half g_H1h[(size_t)BTOT * HYP];
__device__ __half g_H1l[(size_t)BTOT * HYP];
__device__ __half g_HFh[(size_t)BTOT * HYP];
__device__ __half g_HFl[(size_t)BTOT * HYP];
__device__ float g_W1[(size_t)BTOT * 256];           // abs(H1@W1b+b1b)
__device__ float g_B1[(size_t)BTOT * EMB];           // y@Wb1+bb1
__device__ float g_Hv[(size_t)BTOT * EMB];           // relu(y@Wv1+bv1)
__device__ float g_WF[(size_t)BTOT * EMB];           // abs(HF@Wfb+bfb)

// transposed weights: [n][k] single fp16
__device__ __half g_WT0[576 * 512];                  // [W1a|Wfa|Wb1|Wv1]^T
__device__ __half g_WT1[320 * 256];                  // [W1b|Wfb|pad]^T

__device__ __forceinline__ uint32_t smem_u32(const void* p) {
    return (uint32_t)__cvta_generic_to_shared(p);
}

#define LDSM4(r0, r1, r2, r3, addr) \
    asm volatile("ldmatrix.sync.aligned.m8n8.x4.shared.b16 {%0,%1,%2,%3}, [%4];" \
        : "=r"(r0), "=r"(r1), "=r"(r2), "=r"(r3) : "r"(addr))

#define MMA_F16(c, a, b) \
    asm volatile("mma.sync.aligned.m16n8k16.row.col.f32.f16.f16.f32 " \
        "{%0,%1,%2,%3}, {%4,%5,%6,%7}, {%8,%9}, {%0,%1,%2,%3};" \
        : "+f"((c)[0]), "+f"((c)[1]), "+f"((c)[2]), "+f"((c)[3]) \
        : "r"((a)[0]), "r"((a)[1]), "r"((a)[2]), "r"((a)[3]), \
          "r"((b)[0]), "r"((b)[1]))

#define CP16(dst, src) \
    asm volatile("cp.async.cg.shared.global [%0], [%1], 16;" :: "r"(dst), "l"(src))
#define CP_COMMIT() asm volatile("cp.async.commit_group;" ::: "memory")
#define CP_WAIT(n)  asm volatile("cp.async.wait_group %0;" :: "n"(n) : "memory")

__device__ __forceinline__ void h_split(float v, __half& h, __half& l) {
    h = __float2half_rn(v);
    l = __float2half_rn(v - __half2float(h));
}

// =========================================================================
// prep: transpose all GEMM weights to fp16 [n][k] (once per launch, tiny)
// =========================================================================
__global__ __launch_bounds__(256) void prep_split(
    const float* __restrict__ W1a, const float* __restrict__ Wfa,
    const float* __restrict__ Wb1, const float* __restrict__ Wv1,
    const float* __restrict__ W1b, const float* __restrict__ Wfb)
{
    int idx = blockIdx.x * 256 + threadIdx.x;
    if (idx < 576 * 512) {
        int n = idx >> 9, k = idx & 511;
        float v;
        if (n < 256)      v = W1a[k * 256 + n];
        else if (n < 512) v = Wfa[k * 256 + (n - 256)];
        else if (n < 544) v = Wb1[k * 32 + (n - 512)];
        else              v = Wv1[k * 32 + (n - 544)];
        g_WT0[idx] = __float2half_rn(v);
    }
    int idx2 = idx - 576 * 512;
    if (idx2 >= 0 && idx2 < 320 * 256) {
        int n = idx2 >> 8, k = idx2 & 255;
        float v = 0.f;
        if (n < 256)      v = W1b[k * 256 + n];
        else if (n < 288) v = Wfb[k * 32 + (n - 256)];
        g_WT1[idx2] = __float2half_rn(v);
    }
}

// =========================================================================
// k1_mma: token embed on tensor cores (fp16, A split hi/lo, B single).
// A = states viewed as (B*8 = 262144, 64) row-major.
// stage1: E = relu(A @ W_tok + b_tok)   (K=64, N=32)
// stage2: Y = relu(E @ W_yfc + b_yfc)   (K=32, N=64) -> g_Yh/g_Yl
// 128 rows/CTA, 8 warps, each warp owns 16 rows.
// =========================================================================
#define P_A 72
#define P_E 40

#define K1_sAh  0
#define K1_sAl  (K1_sAh + 128 * P_A * 2)      // 18432
#define K1_sBh  (K1_sAl + 128 * P_A * 2)      // 36864 (Wtok^T [32][72])
#define K1_sEh  (K1_sBh + 32 * P_A * 2)       // 41472 (E hi [128][40])
#define K1_sEl  (K1_sEh + 128 * P_E * 2)      // 51712
#define K1_sCh  (K1_sEl + 128 * P_E * 2)      // 61952 (Wyfc^T [64][40])
#define K1_SMEM (K1_sCh + 64 * P_E * 2)       // 67072

__global__ __launch_bounds__(256, 2) void k1_mma(
    const float* __restrict__ states,
    const float* __restrict__ Wt, const float* __restrict__ bt,
    const float* __restrict__ Wy, const float* __restrict__ by)
{
    extern __shared__ __align__(16) char dsm[];
    const uint32_t sb = smem_u32(dsm);
    const int tid  = threadIdx.x;
    const int w    = tid >> 5;
    const int lane = tid & 31;
    const int g    = lane >> 3;
    const int li   = lane & 7;

    // ---- stage inputs: split A, round weights ----
    {
        const float4* S4 = (const float4*)(states + (size_t)blockIdx.x * 128 * 64);
        __half* Ah = (__half*)(dsm + K1_sAh);
        __half* Al = (__half*)(dsm + K1_sAl);
        #pragma unroll
        for (int i = 0; i < 8; i++) {
            int idx = tid + i * 256;
            int row = idx >> 4;
            int k4  = (idx & 15) * 4;
            float4 v = S4[idx];
            int e = row * P_A + k4;
            __half h0,l0,h1,l1,h2,l2,h3,l3;
            h_split(v.x,h0,l0); h_split(v.y,h1,l1);
            h_split(v.z,h2,l2); h_split(v.w,h3,l3);
            __half2 ha = __halves2half2(h0,h1), hb = __halves2half2(h2,h3);
            __half2 la = __halves2half2(l0,l1), lb = __halves2half2(l2,l3);
            *(__half2*)&Ah[e]   = ha;  *(__half2*)&Ah[e+2] = hb;
            *(__half2*)&Al[e]   = la;  *(__half2*)&Al[e+2] = lb;
        }
        __half* Bh = (__half*)(dsm + K1_sBh);
        #pragma unroll
        for (int i = 0; i < 8; i++) {
            int idx = tid + i * 256;
            int n = idx & 31, k = idx >> 5;
            Bh[n * P_A + k] = __float2half_rn(Wt[k * 32 + n]);
        }
        __half* Ch = (__half*)(dsm + K1_sCh);
        #pragma unroll
        for (int i = 0; i < 8; i++) {
            int idx = tid + i * 256;
            int n = idx & 63, k = idx >> 6;
            Ch[n * P_E + k] = __float2half_rn(Wy[k * 64 + n]);
        }
    }
    __syncthreads();

    // ---- stage1: E = relu(A @ Wtok + bt) ----
    {
        float acc[4][4];
        #pragma unroll
        for (int i = 0; i < 4; i++)
            #pragma unroll
            for (int q = 0; q < 4; q++) acc[i][q] = 0.f;

        #pragma unroll
        for (int ks = 0; ks < 4; ks++) {
            const int am = w * 16 + (g & 1) * 8 + li;
            const int ak = (g >> 1) * 8 + ks * 16;
            const int bn = (g >> 1) * 8 + li;
            const int bk = (g & 1) * 8 + ks * 16;
            uint32_t ah[4], al[4], bh[4][2];
            LDSM4(ah[0],ah[1],ah[2],ah[3], sb + K1_sAh + (am * P_A + ak) * 2);
            LDSM4(al[0],al[1],al[2],al[3], sb + K1_sAl + (am * P_A + ak) * 2);
            #pragma unroll
            for (int bp = 0; bp < 2; bp++) {
                LDSM4(bh[2*bp][0], bh[2*bp][1], bh[2*bp+1][0], bh[2*bp+1][1],
                      sb + K1_sBh + ((bn + bp * 16) * P_A + bk) * 2);
            }
            #pragma unroll
            for (int ni = 0; ni < 4; ni++) {
                MMA_F16(acc[ni], ah, bh[ni]);
                MMA_F16(acc[ni], al, bh[ni]);
            }
        }
        __half* Eh = (__half*)(dsm + K1_sEh);
        __half* El = (__half*)(dsm + K1_sEl);
        #pragma unroll
        for (int ni = 0; ni < 4; ni++) {
            int n = ni * 8 + 2 * (lane & 3);
            float b0 = bt[n], b1 = bt[n + 1];
            #pragma unroll
            for (int half = 0; half < 2; half++) {
                int m = w * 16 + (lane >> 2) + half * 8;
                float o0 = fmaxf(acc[ni][half*2+0] + b0, 0.f);
                float o1 = fmaxf(acc[ni][half*2+1] + b1, 0.f);
                __half h0,l0,h1,l1;
                h_split(o0,h0,l0); h_split(o1,h1,l1);
                *(__half2*)&Eh[m * P_E + n] = __halves2half2(h0,h1);
                *(__half2*)&El[m * P_E + n] = __halves2half2(l0,l1);
            }
        }
    }
    __syncthreads();

    // ---- stage2: Y = relu(E @ Wyfc + by), N=64 ----
    {
        float acc[8][4];
        #pragma unroll
        for (int i = 0; i < 8; i++)
            #pragma unroll
            for (int q = 0; q < 4; q++) acc[i][q] = 0.f;

        #pragma unroll
        for (int ks = 0; ks < 2; ks++) {
            const int am = w * 16 + (g & 1) * 8 + li;
            const int ak = (g >> 1) * 8 + ks * 16;
            const int bn = (g >> 1) * 8 + li;
            const int bk = (g & 1) * 8 + ks * 16;
            uint32_t ah[4], al[4], bh[8][2];
            LDSM4(ah[0],ah[1],ah[2],ah[3], sb + K1_sEh + (am * P_E + ak) * 2);
            LDSM4(al[0],al[1],al[2],al[3], sb + K1_sEl + (am * P_E + ak) * 2);
            #pragma unroll
            for (int bp = 0; bp < 4; bp++) {
                LDSM4(bh[2*bp][0], bh[2*bp][1], bh[2*bp+1][0], bh[2*bp+1][1],
                      sb + K1_sCh + ((bn + bp * 16) * P_E + bk) * 2);
            }
            #pragma unroll
            for (int ni = 0; ni < 8; ni++) {
                MMA_F16(acc[ni], ah, bh[ni]);
                MMA_F16(acc[ni], al, bh[ni]);
            }
        }
        #pragma unroll
        for (int ni = 0; ni < 8; ni++) {
            int n = ni * 8 + 2 * (lane & 3);
            float b0 = by[n], b1 = by[n + 1];
            #pragma unroll
            for (int half = 0; half < 2; half++) {
                int m = w * 16 + (lane >> 2) + half * 8;
                size_t R = (size_t)blockIdx.x * 128 + m;
                float o0 = fmaxf(acc[ni][half*2+0] + b0, 0.f);
                float o1 = fmaxf(acc[ni][half*2+1] + b1, 0.f);
                __half h0,l0,h1,l1;
                h_split(o0,h0,l0); h_split(o1,h1,l1);
                *(__half2*)&g_Yh[R * 64 + n] = __halves2half2(h0,h1);
                *(__half2*)&g_Yl[R * 64 + n] = __halves2half2(l0,l1);
            }
        }
    }
}

// =========================================================================
// gemm_mma: fp16 mma.sync, A hi/lo 2-product, B single fp16.
// BM=128, BN=64, BK=32, 256 threads = 8 warps (warp tile 32x32),
// 2-stage cp.async double buffer.
// mode 0: C(B,576) = Y @ WT0 -> H1(h/l) | HF(h/l) | B1 | Hv
// mode 1: blocks 0-3: W1 = abs(H1@W1b+b1b); block 4: WF = abs(HF@Wfb+bfb)
// =========================================================================
#define PITCH 40
#define A_BYTES (128 * PITCH * 2)     // 10240
#define B_BYTES (64 * PITCH * 2)      // 5120
#define STAGE   (2 * A_BYTES + B_BYTES)       // 25600
#define DSMEM   (2 * STAGE)                   // 51200

__global__ __launch_bounds__(256) void gemm_mma(
    int mode,
    const float* __restrict__ b1a, const float* __restrict__ bfa,
    const float* __restrict__ bb1, const float* __restrict__ bv1,
    const float* __restrict__ b1b, const float* __restrict__ bfb)
{
    extern __shared__ __align__(16) char dsm[];
    const uint32_t sbase = smem_u32(dsm);

    const int tid  = threadIdx.x;
    const int wid  = tid >> 5;
    const int lane = tid & 31;
    const int wm   = wid >> 1;          // 0..3 : m-quarter (32 rows)
    const int wn   = wid & 1;           // 0..1 : n-half (32 cols)
    const int nbase = blockIdx.x * 64;
    const int m0    = blockIdx.y * 128;

    const __half *Ah_p, *Al_p, *B_p;
    int lda, ldb, NC;
    if (mode == 0) {
        Ah_p = g_Yh; Al_p = g_Yl; lda = 512;
        B_p = g_WT0; ldb = 512; NC = 16;
    } else {
        if (blockIdx.x == 4) { Ah_p = g_HFh; Al_p = g_HFl; }
        else                 { Ah_p = g_H1h; Al_p = g_H1l; }
        lda = 256;
        B_p = g_WT1; ldb = 256; NC = 8;
    }

    const int ar0 = tid >> 2,  ak0 = (tid & 3) * 8;

    auto issue = [&](int c) {
        const uint32_t st = sbase + (c & 1) * STAGE;
        #pragma unroll
        for (int i = 0; i < 2; i++) {
            int row = ar0 + i * 64;
            uint32_t d = st + row * (PITCH*2) + ak0 * 2;
            const __half* sh = Ah_p + (size_t)(m0 + row) * lda + c * 32 + ak0;
            const __half* sl = Al_p + (size_t)(m0 + row) * lda + c * 32 + ak0;
            CP16(d, sh);
            CP16(d + A_BYTES, sl);
        }
        {
            int n  = ar0;
            uint32_t d = st + 2 * A_BYTES + n * (PITCH*2) + ak0 * 2;
            const __half* sh = B_p + (size_t)(nbase + n) * ldb + c * 32 + ak0;
            CP16(d, sh);
        }
        CP_COMMIT();
    };

    float acc[2][4][4];
    #pragma unroll
    for (int i = 0; i < 2; i++)
        #pragma unroll
        for (int j = 0; j < 4; j++)
            #pragma unroll
            for (int q = 0; q < 4; q++) acc[i][j][q] = 0.f;

    issue(0);

    const int g  = lane >> 3;
    const int li = lane & 7;

    for (int c = 0; c < NC; ++c) {
        if (c + 1 < NC) { issue(c + 1); CP_WAIT(1); }
        else            { CP_WAIT(0); }
        __syncthreads();

        const uint32_t st  = sbase + (c & 1) * STAGE;
        const uint32_t sAh = st;
        const uint32_t sAl = st + A_BYTES;
        const uint32_t sB  = st + 2 * A_BYTES;

        #pragma unroll
        for (int ks = 0; ks < 2; ks++) {
            const int am = wm * 32 + (g & 1) * 8 + li;
            const int ak = (g >> 1) * 8 + ks * 16;
            const int bn = wn * 32 + (g >> 1) * 8 + li;
            const int bk = (g & 1) * 8 + ks * 16;

            uint32_t ah[2][4], al[2][4], bh[4][2];
            #pragma unroll
            for (int mi = 0; mi < 2; mi++) {
                uint32_t a1 = sAh + ((am + mi * 16) * PITCH + ak) * 2;
                LDSM4(ah[mi][0], ah[mi][1], ah[mi][2], ah[mi][3], a1);
                uint32_t a2 = sAl + ((am + mi * 16) * PITCH + ak) * 2;
                LDSM4(al[mi][0], al[mi][1], al[mi][2], al[mi][3], a2);
            }
            #pragma unroll
            for (int bp = 0; bp < 2; bp++) {
                uint32_t a1 = sB + ((bn + bp * 16) * PITCH + bk) * 2;
                LDSM4(bh[2*bp][0], bh[2*bp][1], bh[2*bp+1][0], bh[2*bp+1][1], a1);
            }
            #pragma unroll
            for (int mi = 0; mi < 2; mi++)
                #pragma unroll
                for (int ni = 0; ni < 4; ni++) {
                    MMA_F16(acc[mi][ni], ah[mi], bh[ni]);
                    MMA_F16(acc[mi][ni], al[mi], bh[ni]);
                }
        }
        __syncthreads();
    }

    // ---- epilogue ----
    #pragma unroll
    for (int mi = 0; mi < 2; mi++) {
        #pragma unroll
        for (int ni = 0; ni < 4; ni++) {
            int m  = m0 + wm * 32 + mi * 16 + (lane >> 2);
            int ng = nbase + wn * 32 + ni * 8 + 2 * (lane & 3);
            #pragma unroll
            for (int half = 0; half < 2; half++) {
                int mm = m + half * 8;
                float x0 = acc[mi][ni][half * 2 + 0];
                float x1 = acc[mi][ni][half * 2 + 1];
                if (mode == 0) {
                    if (ng < 256) {
                        float2 b = *(const float2*)&b1a[ng];
                        float o0 = fmaxf(x0 + b.x, 0.f), o1 = fmaxf(x1 + b.y, 0.f);
                        __half h0,l0,h1,l1;
                        h_split(o0,h0,l0); h_split(o1,h1,l1);
                        *(__half2*)&g_H1h[(size_t)mm * 256 + ng] = __halves2half2(h0,h1);
                        *(__half2*)&g_H1l[(size_t)mm * 256 + ng] = __halves2half2(l0,l1);
                    } else if (ng < 512) {
                        int nl = ng - 256;
                        float2 b = *(const float2*)&bfa[nl];
                        float o0 = fmaxf(x0 + b.x, 0.f), o1 = fmaxf(x1 + b.y, 0.f);
                        __half h0,l0,h1,l1;
                        h_split(o0,h0,l0); h_split(o1,h1,l1);
                        *(__half2*)&g_HFh[(size_t)mm * 256 + nl] = __halves2half2(h0,h1);
                        *(__half2*)&g_HFl[(size_t)mm * 256 + nl] = __halves2half2(l0,l1);
                    } else if (ng < 544) {
                        int nl = ng - 512;
                        float2 b = *(const float2*)&bb1[nl];
                        float2 o = make_float2(x0 + b.x, x1 + b.y);
                        *(float2*)&g_B1[(size_t)mm * 32 + nl] = o;
                    } else {
                        int nl = ng - 544;
                        float2 b = *(const float2*)&bv1[nl];
                        float2 o = make_float2(fmaxf(x0 + b.x, 0.f), fmaxf(x1 + b.y, 0.f));
                        *(float2*)&g_Hv[(size_t)mm * 32 + nl] = o;
                    }
                } else {
                    if (nbase < 256) {
                        float2 b = *(const float2*)&b1b[ng];
                        float2 o = make_float2(fabsf(x0 + b.x), fabsf(x1 + b.y));
                        *(float2*)&g_W1[(size_t)mm * 256 + ng] = o;
                    } else {
                        int nl = ng - 256;
                        if (nl < 32) {
                            float2 b = *(const float2*)&bfb[nl];
                            float2 o = make_float2(fabsf(x0 + b.x), fabsf(x1 + b.y));
                            *(float2*)&g_WF[(size_t)mm * 32 + nl] = o;
                        }
                    }
                }
            }
        }
    }
}

// =========================================================================
// K4: final fused epilogue. One warp per row; lane = EMB index e.
// =========================================================================
__device__ __forceinline__ float wred(float v) {
    #pragma unroll
    for (int o = 16; o > 0; o >>= 1) v += __shfl_xor_sync(0xFFFFFFFFu, v, o);
    return v;
}

__global__ __launch_bounds__(256) void k4_final(
    const float* __restrict__ agent_qs,
    const float* __restrict__ Wv2, const float* __restrict__ bv2,
    float* __restrict__ out)
{
    const int w = threadIdx.x >> 5, lane = threadIdx.x & 31;
    const size_t r = (size_t)blockIdx.x * 8 + w;

    const float wv2v = Wv2[lane];

    float q[8];
    #pragma unroll
    for (int a = 0; a < 8; a++) q[a] = agent_qs[r * 8 + a];

    float w1r[8];
    const float* w1p = g_W1 + r * 256;
    #pragma unroll
    for (int a = 0; a < 8; a++) w1r[a] = w1p[a * 32 + lane];

    float x = g_B1[r * 32 + lane];
    #pragma unroll
    for (int a = 0; a < 8; a++) x += q[a] * w1r[a];
    const float h    = (x > 0.f) ? x : expm1f(x);
    const float delu = (h < 0.f) ? expf(h) : 1.f;

    const float wf = g_WF[r * 32 + lane];
    const float hv = g_Hv[r * 32 + lane];

    const float vsum = wred(hv * wv2v);
    const float qt   = wred(h * wf);
    if (lane == 0) out[r] = qt + vsum + bv2[0];

    const float t = delu * wf;
    float* gout = out + BTOT;
    #pragma unroll
    for (int a = 0; a < 8; a++) {
        float s = wred(w1r[a] * t);
        if (lane == a) gout[r * 8 + a] = s;
    }
}

// =========================================================================
extern "C" void kernel_launch(void* const* d_in, const int* in_sizes, int n_in,
                              void* d_out, int out_size)
{
    (void)in_sizes; (void)n_in; (void)out_size;
    const float* agent_qs = (const float*)d_in[0];
    const float* states = (const float*)d_in[2];   // d_in[1]=hist, d_in[3]=obs unused
    const float* W_tok  = (const float*)d_in[4];
    const float* b_tok  = (const float*)d_in[5];
    const float* W_yfc  = (const float*)d_in[6];
    const float* b_yfc  = (const float*)d_in[7];
    const float* W1a    = (const float*)d_in[8];
    const float* b1a    = (const float*)d_in[9];
    const float* W1b    = (const float*)d_in[10];
    const float* b1b    = (const float*)d_in[11];
    const float* Wfa    = (const float*)d_in[12];
    const float* bfa    = (const float*)d_in[13];
    const float* Wfb    = (const float*)d_in[14];
    const float* bfb    = (const float*)d_in[15];
    const float* Wb1    = (const float*)d_in[16];
    const float* bb1    = (const float*)d_in[17];
    const float* Wv1    = (const float*)d_in[18];
    const float* bv1    = (const float*)d_in[19];
    const float* Wv2    = (const float*)d_in[20];
    const float* bv2    = (const float*)d_in[21];
    float* out = (float*)d_out;

    cudaFuncSetAttribute(gemm_mma, cudaFuncAttributeMaxDynamicSharedMemorySize, DSMEM);
    cudaFuncSetAttribute(k1_mma, cudaFuncAttributeMaxDynamicSharedMemorySize, K1_SMEM);

    prep_split<<<1472, 256>>>(W1a, Wfa, Wb1, Wv1, W1b, Wfb);
    k1_mma<<<2048, 256, K1_SMEM>>>(states, W_tok, b_tok, W_yfc, b_yfc);
    gemm_mma<<<dim3(9, BTOT / 128), 256, DSMEM>>>(0, b1a, bfa, bb1, bv1, b1b, bfb);
    gemm_mma<<<dim3(5, BTOT / 128), 256, DSMEM>>>(1, b1a, bfa, bb1, bv1, b1b, bfb);
    k4_final<<<BTOT / 8, 256>>>(agent_qs, Wv2, bv2, out);
}

// round 10
// speedup vs baseline: 2.3257x; 1.3084x over previous
#include <cuda_runtime.h>
#include <cuda_fp16.h>
#include <cstdint>
#include <math.h>

// Problem constants
#define BTOT 32768      // BS*T = 128*256
#define SD   512        // STATE_DIM
#define EMB  32
#define HYP  256

// ---------------- global scratch (no allocations allowed) ----------------
__device__ __half g_Yh [(size_t)BTOT * SD];          // y (single fp16)
__device__ __half g_H1h[(size_t)BTOT * HYP];         // H1 hi/lo (22-bit)
__device__ __half g_H1l[(size_t)BTOT * HYP];
__device__ __half g_HFh[(size_t)BTOT * HYP];
__device__ __half g_HFl[(size_t)BTOT * HYP];
__device__ float g_W1[(size_t)BTOT * 256];           // abs(H1@W1b+b1b)
__device__ float g_B1[(size_t)BTOT * EMB];           // y@Wb1+bb1
__device__ float g_Hv[(size_t)BTOT * EMB];           // relu(y@Wv1+bv1)
__device__ float g_WF[(size_t)BTOT * EMB];           // abs(HF@Wfb+bfb)

// transposed weights: [n][k] single fp16
__device__ __half g_WT0[576 * 512];                  // [W1a|Wfa|Wb1|Wv1]^T
__device__ __half g_WT1[320 * 256];                  // [W1b|Wfb|pad]^T

__device__ __forceinline__ uint32_t smem_u32(const void* p) {
    return (uint32_t)__cvta_generic_to_shared(p);
}

#define LDSM4(r0, r1, r2, r3, addr) \
    asm volatile("ldmatrix.sync.aligned.m8n8.x4.shared.b16 {%0,%1,%2,%3}, [%4];" \
        : "=r"(r0), "=r"(r1), "=r"(r2), "=r"(r3) : "r"(addr))

#define MMA_F16(c, a, b) \
    asm volatile("mma.sync.aligned.m16n8k16.row.col.f32.f16.f16.f32 " \
        "{%0,%1,%2,%3}, {%4,%5,%6,%7}, {%8,%9}, {%0,%1,%2,%3};" \
        : "+f"((c)[0]), "+f"((c)[1]), "+f"((c)[2]), "+f"((c)[3]) \
        : "r"((a)[0]), "r"((a)[1]), "r"((a)[2]), "r"((a)[3]), \
          "r"((b)[0]), "r"((b)[1]))

#define CP16(dst, src) \
    asm volatile("cp.async.cg.shared.global [%0], [%1], 16;" :: "r"(dst), "l"(src))
#define CP_COMMIT() asm volatile("cp.async.commit_group;" ::: "memory")
#define CP_WAIT(n)  asm volatile("cp.async.wait_group %0;" :: "n"(n) : "memory")

__device__ __forceinline__ void h_split(float v, __half& h, __half& l) {
    h = __float2half_rn(v);
    l = __float2half_rn(v - __half2float(h));
}

// =========================================================================
// prep: transpose all GEMM weights to fp16 [n][k] (once per launch, tiny)
// =========================================================================
__global__ __launch_bounds__(256) void prep_split(
    const float* __restrict__ W1a, const float* __restrict__ Wfa,
    const float* __restrict__ Wb1, const float* __restrict__ Wv1,
    const float* __restrict__ W1b, const float* __restrict__ Wfb)
{
    int idx = blockIdx.x * 256 + threadIdx.x;
    if (idx < 576 * 512) {
        int n = idx >> 9, k = idx & 511;
        float v;
        if (n < 256)      v = W1a[k * 256 + n];
        else if (n < 512) v = Wfa[k * 256 + (n - 256)];
        else if (n < 544) v = Wb1[k * 32 + (n - 512)];
        else              v = Wv1[k * 32 + (n - 544)];
        g_WT0[idx] = __float2half_rn(v);
    }
    int idx2 = idx - 576 * 512;
    if (idx2 >= 0 && idx2 < 320 * 256) {
        int n = idx2 >> 8, k = idx2 & 255;
        float v = 0.f;
        if (n < 256)      v = W1b[k * 256 + n];
        else if (n < 288) v = Wfb[k * 32 + (n - 256)];
        g_WT1[idx2] = __float2half_rn(v);
    }
}

// =========================================================================
// k1_mma: token embed on tensor cores (fp16, A split hi/lo, B single).
// stage1: E = relu(A @ W_tok + b_tok)   (K=64, N=32)
// stage2: Y = relu(E @ W_yfc + b_yfc)   (K=32, N=64) -> g_Yh (single fp16)
// 128 rows/CTA, 8 warps, each warp owns 16 rows.
// =========================================================================
#define P_A 72
#define P_E 40

#define K1_sAh  0
#define K1_sAl  (K1_sAh + 128 * P_A * 2)      // 18432
#define K1_sBh  (K1_sAl + 128 * P_A * 2)      // 36864 (Wtok^T [32][72])
#define K1_sEh  (K1_sBh + 32 * P_A * 2)       // 41472 (E hi [128][40])
#define K1_sEl  (K1_sEh + 128 * P_E * 2)      // 51712
#define K1_sCh  (K1_sEl + 128 * P_E * 2)      // 61952 (Wyfc^T [64][40])
#define K1_SMEM (K1_sCh + 64 * P_E * 2)       // 67072

__global__ __launch_bounds__(256, 2) void k1_mma(
    const float* __restrict__ states,
    const float* __restrict__ Wt, const float* __restrict__ bt,
    const float* __restrict__ Wy, const float* __restrict__ by)
{
    extern __shared__ __align__(16) char dsm[];
    const uint32_t sb = smem_u32(dsm);
    const int tid  = threadIdx.x;
    const int w    = tid >> 5;
    const int lane = tid & 31;
    const int g    = lane >> 3;
    const int li   = lane & 7;

    // ---- stage inputs: split A, round weights ----
    {
        const float4* S4 = (const float4*)(states + (size_t)blockIdx.x * 128 * 64);
        __half* Ah = (__half*)(dsm + K1_sAh);
        __half* Al = (__half*)(dsm + K1_sAl);
        #pragma unroll
        for (int i = 0; i < 8; i++) {
            int idx = tid + i * 256;
            int row = idx >> 4;
            int k4  = (idx & 15) * 4;
            float4 v = S4[idx];
            int e = row * P_A + k4;
            __half h0,l0,h1,l1,h2,l2,h3,l3;
            h_split(v.x,h0,l0); h_split(v.y,h1,l1);
            h_split(v.z,h2,l2); h_split(v.w,h3,l3);
            *(__half2*)&Ah[e]   = __halves2half2(h0,h1);
            *(__half2*)&Ah[e+2] = __halves2half2(h2,h3);
            *(__half2*)&Al[e]   = __halves2half2(l0,l1);
            *(__half2*)&Al[e+2] = __halves2half2(l2,l3);
        }
        __half* Bh = (__half*)(dsm + K1_sBh);
        #pragma unroll
        for (int i = 0; i < 8; i++) {
            int idx = tid + i * 256;
            int n = idx & 31, k = idx >> 5;
            Bh[n * P_A + k] = __float2half_rn(Wt[k * 32 + n]);
        }
        __half* Ch = (__half*)(dsm + K1_sCh);
        #pragma unroll
        for (int i = 0; i < 8; i++) {
            int idx = tid + i * 256;
            int n = idx & 63, k = idx >> 6;
            Ch[n * P_E + k] = __float2half_rn(Wy[k * 64 + n]);
        }
    }
    __syncthreads();

    // ---- stage1: E = relu(A @ Wtok + bt) ----
    {
        float acc[4][4];
        #pragma unroll
        for (int i = 0; i < 4; i++)
            #pragma unroll
            for (int q = 0; q < 4; q++) acc[i][q] = 0.f;

        #pragma unroll
        for (int ks = 0; ks < 4; ks++) {
            const int am = w * 16 + (g & 1) * 8 + li;
            const int ak = (g >> 1) * 8 + ks * 16;
            const int bn = (g >> 1) * 8 + li;
            const int bk = (g & 1) * 8 + ks * 16;
            uint32_t ah[4], al[4], bh[4][2];
            LDSM4(ah[0],ah[1],ah[2],ah[3], sb + K1_sAh + (am * P_A + ak) * 2);
            LDSM4(al[0],al[1],al[2],al[3], sb + K1_sAl + (am * P_A + ak) * 2);
            #pragma unroll
            for (int bp = 0; bp < 2; bp++) {
                LDSM4(bh[2*bp][0], bh[2*bp][1], bh[2*bp+1][0], bh[2*bp+1][1],
                      sb + K1_sBh + ((bn + bp * 16) * P_A + bk) * 2);
            }
            #pragma unroll
            for (int ni = 0; ni < 4; ni++) {
                MMA_F16(acc[ni], ah, bh[ni]);
                MMA_F16(acc[ni], al, bh[ni]);
            }
        }
        __half* Eh = (__half*)(dsm + K1_sEh);
        __half* El = (__half*)(dsm + K1_sEl);
        #pragma unroll
        for (int ni = 0; ni < 4; ni++) {
            int n = ni * 8 + 2 * (lane & 3);
            float b0 = bt[n], b1 = bt[n + 1];
            #pragma unroll
            for (int half = 0; half < 2; half++) {
                int m = w * 16 + (lane >> 2) + half * 8;
                float o0 = fmaxf(acc[ni][half*2+0] + b0, 0.f);
                float o1 = fmaxf(acc[ni][half*2+1] + b1, 0.f);
                __half h0,l0,h1,l1;
                h_split(o0,h0,l0); h_split(o1,h1,l1);
                *(__half2*)&Eh[m * P_E + n] = __halves2half2(h0,h1);
                *(__half2*)&El[m * P_E + n] = __halves2half2(l0,l1);
            }
        }
    }
    __syncthreads();

    // ---- stage2: Y = relu(E @ Wyfc + by), N=64 -> single fp16 ----
    {
        float acc[8][4];
        #pragma unroll
        for (int i = 0; i < 8; i++)
            #pragma unroll
            for (int q = 0; q < 4; q++) acc[i][q] = 0.f;

        #pragma unroll
        for (int ks = 0; ks < 2; ks++) {
            const int am = w * 16 + (g & 1) * 8 + li;
            const int ak = (g >> 1) * 8 + ks * 16;
            const int bn = (g >> 1) * 8 + li;
            const int bk = (g & 1) * 8 + ks * 16;
            uint32_t ah[4], al[4], bh[8][2];
            LDSM4(ah[0],ah[1],ah[2],ah[3], sb + K1_sEh + (am * P_E + ak) * 2);
            LDSM4(al[0],al[1],al[2],al[3], sb + K1_sEl + (am * P_E + ak) * 2);
            #pragma unroll
            for (int bp = 0; bp < 4; bp++) {
                LDSM4(bh[2*bp][0], bh[2*bp][1], bh[2*bp+1][0], bh[2*bp+1][1],
                      sb + K1_sCh + ((bn + bp * 16) * P_E + bk) * 2);
            }
            #pragma unroll
            for (int ni = 0; ni < 8; ni++) {
                MMA_F16(acc[ni], ah, bh[ni]);
                MMA_F16(acc[ni], al, bh[ni]);
            }
        }
        #pragma unroll
        for (int ni = 0; ni < 8; ni++) {
            int n = ni * 8 + 2 * (lane & 3);
            float b0 = by[n], b1 = by[n + 1];
            #pragma unroll
            for (int half = 0; half < 2; half++) {
                int m = w * 16 + (lane >> 2) + half * 8;
                size_t R = (size_t)blockIdx.x * 128 + m;
                float o0 = fmaxf(acc[ni][half*2+0] + b0, 0.f);
                float o1 = fmaxf(acc[ni][half*2+1] + b1, 0.f);
                *(__half2*)&g_Yh[R * 64 + n] =
                    __halves2half2(__float2half_rn(o0), __float2half_rn(o1));
            }
        }
    }
}

// =========================================================================
// gemm_mma<MODE>: fp16 mma.sync.
// MODE 0: single-product (A = Yh fp16, B fp16), C(B,576) = Y @ WT0
//         -> H1(h/l) | HF(h/l) | B1 | Hv
// MODE 1: 2-product (A hi/lo), blocks 0-3: W1 = abs(H1@W1b+b1b);
//         block 4: WF = abs(HF@Wfb+bfb)
// BM=128, BN=64, BK=32, 256 threads = 8 warps (warp tile 32x32),
// 2-stage cp.async double buffer.
// =========================================================================
#define PITCH 40
#define A_BYTES (128 * PITCH * 2)     // 10240
#define B_BYTES (64 * PITCH * 2)      // 5120
#define STAGE0  (A_BYTES + B_BYTES)           // 15360
#define STAGE1  (2 * A_BYTES + B_BYTES)       // 25600
#define DSMEM0  (2 * STAGE0)                  // 30720
#define DSMEM1  (2 * STAGE1)                  // 51200

template<int MODE>
__global__ __launch_bounds__(256) void gemm_mma(
    const float* __restrict__ b1a, const float* __restrict__ bfa,
    const float* __restrict__ bb1, const float* __restrict__ bv1,
    const float* __restrict__ b1b, const float* __restrict__ bfb)
{
    extern __shared__ __align__(16) char dsm[];
    const uint32_t sbase = smem_u32(dsm);

    constexpr int NSPLIT = (MODE == 0) ? 1 : 2;            // A matrices staged
    constexpr int STG    = (MODE == 0) ? STAGE0 : STAGE1;

    const int tid  = threadIdx.x;
    const int wid  = tid >> 5;
    const int lane = tid & 31;
    const int wm   = wid >> 1;          // 0..3 : m-quarter (32 rows)
    const int wn   = wid & 1;           // 0..1 : n-half (32 cols)
    const int nbase = blockIdx.x * 64;
    const int m0    = blockIdx.y * 128;

    const __half *Ah_p, *Al_p, *B_p;
    int lda, ldb, NC;
    if (MODE == 0) {
        Ah_p = g_Yh; Al_p = g_Yh; lda = 512;
        B_p = g_WT0; ldb = 512; NC = 16;
    } else {
        if (blockIdx.x == 4) { Ah_p = g_HFh; Al_p = g_HFl; }
        else                 { Ah_p = g_H1h; Al_p = g_H1l; }
        lda = 256;
        B_p = g_WT1; ldb = 256; NC = 8;
    }

    const int ar0 = tid >> 2,  ak0 = (tid & 3) * 8;

    auto issue = [&](int c) {
        const uint32_t st = sbase + (c & 1) * STG;
        #pragma unroll
        for (int i = 0; i < 2; i++) {
            int row = ar0 + i * 64;
            uint32_t d = st + row * (PITCH*2) + ak0 * 2;
            const __half* sh = Ah_p + (size_t)(m0 + row) * lda + c * 32 + ak0;
            CP16(d, sh);
            if (NSPLIT == 2) {
                const __half* sl = Al_p + (size_t)(m0 + row) * lda + c * 32 + ak0;
                CP16(d + A_BYTES, sl);
            }
        }
        {
            int n  = ar0;
            uint32_t d = st + NSPLIT * A_BYTES + n * (PITCH*2) + ak0 * 2;
            const __half* sh = B_p + (size_t)(nbase + n) * ldb + c * 32 + ak0;
            CP16(d, sh);
        }
        CP_COMMIT();
    };

    float acc[2][4][4];
    #pragma unroll
    for (int i = 0; i < 2; i++)
        #pragma unroll
        for (int j = 0; j < 4; j++)
            #pragma unroll
            for (int q = 0; q < 4; q++) acc[i][j][q] = 0.f;

    issue(0);

    const int g  = lane >> 3;
    const int li = lane & 7;

    for (int c = 0; c < NC; ++c) {
        if (c + 1 < NC) { issue(c + 1); CP_WAIT(1); }
        else            { CP_WAIT(0); }
        __syncthreads();

        const uint32_t st  = sbase + (c & 1) * STG;
        const uint32_t sAh = st;
        const uint32_t sAl = st + A_BYTES;
        const uint32_t sB  = st + NSPLIT * A_BYTES;

        #pragma unroll
        for (int ks = 0; ks < 2; ks++) {
            const int am = wm * 32 + (g & 1) * 8 + li;
            const int ak = (g >> 1) * 8 + ks * 16;
            const int bn = wn * 32 + (g >> 1) * 8 + li;
            const int bk = (g & 1) * 8 + ks * 16;

            uint32_t ah[2][4], al[2][4], bh[4][2];
            #pragma unroll
            for (int mi = 0; mi < 2; mi++) {
                uint32_t a1 = sAh + ((am + mi * 16) * PITCH + ak) * 2;
                LDSM4(ah[mi][0], ah[mi][1], ah[mi][2], ah[mi][3], a1);
                if (NSPLIT == 2) {
                    uint32_t a2 = sAl + ((am + mi * 16) * PITCH + ak) * 2;
                    LDSM4(al[mi][0], al[mi][1], al[mi][2], al[mi][3], a2);
                }
            }
            #pragma unroll
            for (int bp = 0; bp < 2; bp++) {
                uint32_t a1 = sB + ((bn + bp * 16) * PITCH + bk) * 2;
                LDSM4(bh[2*bp][0], bh[2*bp][1], bh[2*bp+1][0], bh[2*bp+1][1], a1);
            }
            #pragma unroll
            for (int mi = 0; mi < 2; mi++)
                #pragma unroll
                for (int ni = 0; ni < 4; ni++) {
                    MMA_F16(acc[mi][ni], ah[mi], bh[ni]);
                    if (NSPLIT == 2) MMA_F16(acc[mi][ni], al[mi], bh[ni]);
                }
        }
        __syncthreads();
    }

    // ---- epilogue ----
    #pragma unroll
    for (int mi = 0; mi < 2; mi++) {
        #pragma unroll
        for (int ni = 0; ni < 4; ni++) {
            int m  = m0 + wm * 32 + mi * 16 + (lane >> 2);
            int ng = nbase + wn * 32 + ni * 8 + 2 * (lane & 3);
            #pragma unroll
            for (int half = 0; half < 2; half++) {
                int mm = m + half * 8;
                float x0 = acc[mi][ni][half * 2 + 0];
                float x1 = acc[mi][ni][half * 2 + 1];
                if (MODE == 0) {
                    if (ng < 256) {
                        float2 b = *(const float2*)&b1a[ng];
                        float o0 = fmaxf(x0 + b.x, 0.f), o1 = fmaxf(x1 + b.y, 0.f);
                        __half h0,l0,h1,l1;
                        h_split(o0,h0,l0); h_split(o1,h1,l1);
                        *(__half2*)&g_H1h[(size_t)mm * 256 + ng] = __halves2half2(h0,h1);
                        *(__half2*)&g_H1l[(size_t)mm * 256 + ng] = __halves2half2(l0,l1);
                    } else if (ng < 512) {
                        int nl = ng - 256;
                        float2 b = *(const float2*)&bfa[nl];
                        float o0 = fmaxf(x0 + b.x, 0.f), o1 = fmaxf(x1 + b.y, 0.f);
                        __half h0,l0,h1,l1;
                        h_split(o0,h0,l0); h_split(o1,h1,l1);
                        *(__half2*)&g_HFh[(size_t)mm * 256 + nl] = __halves2half2(h0,h1);
                        *(__half2*)&g_HFl[(size_t)mm * 256 + nl] = __halves2half2(l0,l1);
                    } else if (ng < 544) {
                        int nl = ng - 512;
                        float2 b = *(const float2*)&bb1[nl];
                        float2 o = make_float2(x0 + b.x, x1 + b.y);
                        *(float2*)&g_B1[(size_t)mm * 32 + nl] = o;
                    } else {
                        int nl = ng - 544;
                        float2 b = *(const float2*)&bv1[nl];
                        float2 o = make_float2(fmaxf(x0 + b.x, 0.f), fmaxf(x1 + b.y, 0.f));
                        *(float2*)&g_Hv[(size_t)mm * 32 + nl] = o;
                    }
                } else {
                    if (nbase < 256) {
                        float2 b = *(const float2*)&b1b[ng];
                        float2 o = make_float2(fabsf(x0 + b.x), fabsf(x1 + b.y));
                        *(float2*)&g_W1[(size_t)mm * 256 + ng] = o;
                    } else {
                        int nl = ng - 256;
                        if (nl < 32) {
                            float2 b = *(const float2*)&bfb[nl];
                            float2 o = make_float2(fabsf(x0 + b.x), fabsf(x1 + b.y));
                            *(float2*)&g_WF[(size_t)mm * 32 + nl] = o;
                        }
                    }
                }
            }
        }
    }
}

// =========================================================================
// K4: final fused epilogue. One warp per row; lane = EMB index e.
// =========================================================================
__device__ __forceinline__ float wred(float v) {
    #pragma unroll
    for (int o = 16; o > 0; o >>= 1) v += __shfl_xor_sync(0xFFFFFFFFu, v, o);
    return v;
}

__global__ __launch_bounds__(256) void k4_final(
    const float* __restrict__ agent_qs,
    const float* __restrict__ Wv2, const float* __restrict__ bv2,
    float* __restrict__ out)
{
    const int w = threadIdx.x >> 5, lane = threadIdx.x & 31;
    const size_t r = (size_t)blockIdx.x * 8 + w;

    const float wv2v = Wv2[lane];

    float q[8];
    #pragma unroll
    for (int a = 0; a < 8; a++) q[a] = agent_qs[r * 8 + a];

    float w1r[8];
    const float* w1p = g_W1 + r * 256;
    #pragma unroll
    for (int a = 0; a < 8; a++) w1r[a] = w1p[a * 32 + lane];

    float x = g_B1[r * 32 + lane];
    #pragma unroll
    for (int a = 0; a < 8; a++) x += q[a] * w1r[a];
    const float h    = (x > 0.f) ? x : expm1f(x);
    const float delu = (h < 0.f) ? expf(h) : 1.f;

    const float wf = g_WF[r * 32 + lane];
    const float hv = g_Hv[r * 32 + lane];

    const float vsum = wred(hv * wv2v);
    const float qt   = wred(h * wf);
    if (lane == 0) out[r] = qt + vsum + bv2[0];

    const float t = delu * wf;
    float* gout = out + BTOT;
    #pragma unroll
    for (int a = 0; a < 8; a++) {
        float s = wred(w1r[a] * t);
        if (lane == a) gout[r * 8 + a] = s;
    }
}

// =========================================================================
extern "C" void kernel_launch(void* const* d_in, const int* in_sizes, int n_in,
                              void* d_out, int out_size)
{
    (void)in_sizes; (void)n_in; (void)out_size;
    const float* agent_qs = (const float*)d_in[0];
    const float* states = (const float*)d_in[2];   // d_in[1]=hist, d_in[3]=obs unused
    const float* W_tok  = (const float*)d_in[4];
    const float* b_tok  = (const float*)d_in[5];
    const float* W_yfc  = (const float*)d_in[6];
    const float* b_yfc  = (const float*)d_in[7];
    const float* W1a    = (const float*)d_in[8];
    const float* b1a    = (const float*)d_in[9];
    const float* W1b    = (const float*)d_in[10];
    const float* b1b    = (const float*)d_in[11];
    const float* Wfa    = (const float*)d_in[12];
    const float* bfa    = (const float*)d_in[13];
    const float* Wfb    = (const float*)d_in[14];
    const float* bfb    = (const float*)d_in[15];
    const float* Wb1    = (const float*)d_in[16];
    const float* bb1    = (const float*)d_in[17];
    const float* Wv1    = (const float*)d_in[18];
    const float* bv1    = (const float*)d_in[19];
    const float* Wv2    = (const float*)d_in[20];
    const float* bv2    = (const float*)d_in[21];
    float* out = (float*)d_out;

    cudaFuncSetAttribute(gemm_mma<0>, cudaFuncAttributeMaxDynamicSharedMemorySize, DSMEM0);
    cudaFuncSetAttribute(gemm_mma<1>, cudaFuncAttributeMaxDynamicSharedMemorySize, DSMEM1);
    cudaFuncSetAttribute(k1_mma, cudaFuncAttributeMaxDynamicSharedMemorySize, K1_SMEM);

    prep_split<<<1472, 256>>>(W1a, Wfa, Wb1, Wv1, W1b, Wfb);
    k1_mma<<<2048, 256, K1_SMEM>>>(states, W_tok, b_tok, W_yfc, b_yfc);
    gemm_mma<0><<<dim3(9, BTOT / 128), 256, DSMEM0>>>(b1a, bfa, bb1, bv1, b1b, bfb);
    gemm_mma<1><<<dim3(5, BTOT / 128), 256, DSMEM1>>>(b1a, bfa, bb1, bv1, b1b, bfb);
    k4_final<<<BTOT / 8, 256>>>(agent_qs, Wv2, bv2, out);
}

// round 11
// speedup vs baseline: 2.6237x; 1.1282x over previous
#include <cuda_runtime.h>
#include <cuda_fp16.h>
#include <cstdint>
#include <math.h>

// Problem constants
#define BTOT 32768      // BS*T = 128*256
#define SD   512        // STATE_DIM
#define EMB  32
#define HYP  256

// ---------------- global scratch (no allocations allowed) ----------------
__device__ __half g_Yh [(size_t)BTOT * SD];          // y (single fp16)
__device__ __half g_H1h[(size_t)BTOT * HYP];         // H1 (single fp16)
__device__ __half g_HFh[(size_t)BTOT * HYP];         // HF (single fp16)
__device__ float g_W1[(size_t)BTOT * 256];           // abs(H1@W1b+b1b)
__device__ float g_B1[(size_t)BTOT * EMB];           // y@Wb1+bb1
__device__ float g_Hv[(size_t)BTOT * EMB];           // relu(y@Wv1+bv1)
__device__ float g_WF[(size_t)BTOT * EMB];           // abs(HF@Wfb+bfb)

// transposed weights: [n][k] single fp16
__device__ __half g_WT0[576 * 512];                  // [W1a|Wfa|Wb1|Wv1]^T
__device__ __half g_WT1[320 * 256];                  // [W1b|Wfb|pad]^T

__device__ __forceinline__ uint32_t smem_u32(const void* p) {
    return (uint32_t)__cvta_generic_to_shared(p);
}

#define LDSM4(r0, r1, r2, r3, addr) \
    asm volatile("ldmatrix.sync.aligned.m8n8.x4.shared.b16 {%0,%1,%2,%3}, [%4];" \
        : "=r"(r0), "=r"(r1), "=r"(r2), "=r"(r3) : "r"(addr))

#define MMA_F16(c, a, b) \
    asm volatile("mma.sync.aligned.m16n8k16.row.col.f32.f16.f16.f32 " \
        "{%0,%1,%2,%3}, {%4,%5,%6,%7}, {%8,%9}, {%0,%1,%2,%3};" \
        : "+f"((c)[0]), "+f"((c)[1]), "+f"((c)[2]), "+f"((c)[3]) \
        : "r"((a)[0]), "r"((a)[1]), "r"((a)[2]), "r"((a)[3]), \
          "r"((b)[0]), "r"((b)[1]))

#define CP16(dst, src) \
    asm volatile("cp.async.cg.shared.global [%0], [%1], 16;" :: "r"(dst), "l"(src))
#define CP_COMMIT() asm volatile("cp.async.commit_group;" ::: "memory")
#define CP_WAIT(n)  asm volatile("cp.async.wait_group %0;" :: "n"(n) : "memory")

__device__ __forceinline__ void h_split(float v, __half& h, __half& l) {
    h = __float2half_rn(v);
    l = __float2half_rn(v - __half2float(h));
}

// =========================================================================
// prep: transpose all GEMM weights to fp16 [n][k] (once per launch, tiny)
// =========================================================================
__global__ __launch_bounds__(256) void prep_split(
    const float* __restrict__ W1a, const float* __restrict__ Wfa,
    const float* __restrict__ Wb1, const float* __restrict__ Wv1,
    const float* __restrict__ W1b, const float* __restrict__ Wfb)
{
    int idx = blockIdx.x * 256 + threadIdx.x;
    if (idx < 576 * 512) {
        int n = idx >> 9, k = idx & 511;
        float v;
        if (n < 256)      v = W1a[k * 256 + n];
        else if (n < 512) v = Wfa[k * 256 + (n - 256)];
        else if (n < 544) v = Wb1[k * 32 + (n - 512)];
        else              v = Wv1[k * 32 + (n - 544)];
        g_WT0[idx] = __float2half_rn(v);
    }
    int idx2 = idx - 576 * 512;
    if (idx2 >= 0 && idx2 < 320 * 256) {
        int n = idx2 >> 8, k = idx2 & 255;
        float v = 0.f;
        if (n < 256)      v = W1b[k * 256 + n];
        else if (n < 288) v = Wfb[k * 32 + (n - 256)];
        g_WT1[idx2] = __float2half_rn(v);
    }
}

// =========================================================================
// k1_mma: token embed on tensor cores (fp16, A split hi/lo, B single).
// stage1: E = relu(A @ W_tok + b_tok)   (K=64, N=32)
// stage2: Y = relu(E @ W_yfc + b_yfc)   (K=32, N=64) -> g_Yh (single fp16)
// 128 rows/CTA, 8 warps, each warp owns 16 rows.
// =========================================================================
#define P_A 72
#define P_E 40

#define K1_sAh  0
#define K1_sAl  (K1_sAh + 128 * P_A * 2)      // 18432
#define K1_sBh  (K1_sAl + 128 * P_A * 2)      // 36864 (Wtok^T [32][72])
#define K1_sEh  (K1_sBh + 32 * P_A * 2)       // 41472 (E hi [128][40])
#define K1_sEl  (K1_sEh + 128 * P_E * 2)      // 51712
#define K1_sCh  (K1_sEl + 128 * P_E * 2)      // 61952 (Wyfc^T [64][40])
#define K1_SMEM (K1_sCh + 64 * P_E * 2)       // 67072

__global__ __launch_bounds__(256, 2) void k1_mma(
    const float* __restrict__ states,
    const float* __restrict__ Wt, const float* __restrict__ bt,
    const float* __restrict__ Wy, const float* __restrict__ by)
{
    extern __shared__ __align__(16) char dsm[];
    const uint32_t sb = smem_u32(dsm);
    const int tid  = threadIdx.x;
    const int w    = tid >> 5;
    const int lane = tid & 31;
    const int g    = lane >> 3;
    const int li   = lane & 7;

    // ---- stage inputs: split A, round weights ----
    {
        const float4* S4 = (const float4*)(states + (size_t)blockIdx.x * 128 * 64);
        __half* Ah = (__half*)(dsm + K1_sAh);
        __half* Al = (__half*)(dsm + K1_sAl);
        #pragma unroll
        for (int i = 0; i < 8; i++) {
            int idx = tid + i * 256;
            int row = idx >> 4;
            int k4  = (idx & 15) * 4;
            float4 v = S4[idx];
            int e = row * P_A + k4;
            __half h0,l0,h1,l1,h2,l2,h3,l3;
            h_split(v.x,h0,l0); h_split(v.y,h1,l1);
            h_split(v.z,h2,l2); h_split(v.w,h3,l3);
            *(__half2*)&Ah[e]   = __halves2half2(h0,h1);
            *(__half2*)&Ah[e+2] = __halves2half2(h2,h3);
            *(__half2*)&Al[e]   = __halves2half2(l0,l1);
            *(__half2*)&Al[e+2] = __halves2half2(l2,l3);
        }
        __half* Bh = (__half*)(dsm + K1_sBh);
        #pragma unroll
        for (int i = 0; i < 8; i++) {
            int idx = tid + i * 256;
            int n = idx & 31, k = idx >> 5;
            Bh[n * P_A + k] = __float2half_rn(Wt[k * 32 + n]);
        }
        __half* Ch = (__half*)(dsm + K1_sCh);
        #pragma unroll
        for (int i = 0; i < 8; i++) {
            int idx = tid + i * 256;
            int n = idx & 63, k = idx >> 6;
            Ch[n * P_E + k] = __float2half_rn(Wy[k * 64 + n]);
        }
    }
    __syncthreads();

    // ---- stage1: E = relu(A @ Wtok + bt) ----
    {
        float acc[4][4];
        #pragma unroll
        for (int i = 0; i < 4; i++)
            #pragma unroll
            for (int q = 0; q < 4; q++) acc[i][q] = 0.f;

        #pragma unroll
        for (int ks = 0; ks < 4; ks++) {
            const int am = w * 16 + (g & 1) * 8 + li;
            const int ak = (g >> 1) * 8 + ks * 16;
            const int bn = (g >> 1) * 8 + li;
            const int bk = (g & 1) * 8 + ks * 16;
            uint32_t ah[4], al[4], bh[4][2];
            LDSM4(ah[0],ah[1],ah[2],ah[3], sb + K1_sAh + (am * P_A + ak) * 2);
            LDSM4(al[0],al[1],al[2],al[3], sb + K1_sAl + (am * P_A + ak) * 2);
            #pragma unroll
            for (int bp = 0; bp < 2; bp++) {
                LDSM4(bh[2*bp][0], bh[2*bp][1], bh[2*bp+1][0], bh[2*bp+1][1],
                      sb + K1_sBh + ((bn + bp * 16) * P_A + bk) * 2);
            }
            #pragma unroll
            for (int ni = 0; ni < 4; ni++) {
                MMA_F16(acc[ni], ah, bh[ni]);
                MMA_F16(acc[ni], al, bh[ni]);
            }
        }
        __half* Eh = (__half*)(dsm + K1_sEh);
        __half* El = (__half*)(dsm + K1_sEl);
        #pragma unroll
        for (int ni = 0; ni < 4; ni++) {
            int n = ni * 8 + 2 * (lane & 3);
            float b0 = bt[n], b1 = bt[n + 1];
            #pragma unroll
            for (int half = 0; half < 2; half++) {
                int m = w * 16 + (lane >> 2) + half * 8;
                float o0 = fmaxf(acc[ni][half*2+0] + b0, 0.f);
                float o1 = fmaxf(acc[ni][half*2+1] + b1, 0.f);
                __half h0,l0,h1,l1;
                h_split(o0,h0,l0); h_split(o1,h1,l1);
                *(__half2*)&Eh[m * P_E + n] = __halves2half2(h0,h1);
                *(__half2*)&El[m * P_E + n] = __halves2half2(l0,l1);
            }
        }
    }
    __syncthreads();

    // ---- stage2: Y = relu(E @ Wyfc + by), N=64 -> single fp16 ----
    {
        float acc[8][4];
        #pragma unroll
        for (int i = 0; i < 8; i++)
            #pragma unroll
            for (int q = 0; q < 4; q++) acc[i][q] = 0.f;

        #pragma unroll
        for (int ks = 0; ks < 2; ks++) {
            const int am = w * 16 + (g & 1) * 8 + li;
            const int ak = (g >> 1) * 8 + ks * 16;
            const int bn = (g >> 1) * 8 + li;
            const int bk = (g & 1) * 8 + ks * 16;
            uint32_t ah[4], al[4], bh[8][2];
            LDSM4(ah[0],ah[1],ah[2],ah[3], sb + K1_sEh + (am * P_E + ak) * 2);
            LDSM4(al[0],al[1],al[2],al[3], sb + K1_sEl + (am * P_E + ak) * 2);
            #pragma unroll
            for (int bp = 0; bp < 4; bp++) {
                LDSM4(bh[2*bp][0], bh[2*bp][1], bh[2*bp+1][0], bh[2*bp+1][1],
                      sb + K1_sCh + ((bn + bp * 16) * P_E + bk) * 2);
            }
            #pragma unroll
            for (int ni = 0; ni < 8; ni++) {
                MMA_F16(acc[ni], ah, bh[ni]);
                MMA_F16(acc[ni], al, bh[ni]);
            }
        }
        #pragma unroll
        for (int ni = 0; ni < 8; ni++) {
            int n = ni * 8 + 2 * (lane & 3);
            float b0 = by[n], b1 = by[n + 1];
            #pragma unroll
            for (int half = 0; half < 2; half++) {
                int m = w * 16 + (lane >> 2) + half * 8;
                size_t R = (size_t)blockIdx.x * 128 + m;
                float o0 = fmaxf(acc[ni][half*2+0] + b0, 0.f);
                float o1 = fmaxf(acc[ni][half*2+1] + b1, 0.f);
                *(__half2*)&g_Yh[R * 64 + n] =
                    __halves2half2(__float2half_rn(o0), __float2half_rn(o1));
            }
        }
    }
}

// =========================================================================
// gemm_mma<MODE>: fp16 mma.sync, single-product (A fp16, B fp16).
// MODE 0: C(B,576) = Y @ WT0 -> H1 | HF | B1 | Hv
// MODE 1: blocks 0-3: W1 = abs(H1@W1b+b1b); block 4: WF = abs(HF@Wfb+bfb)
// BM=128, BN=64, BK=32, 256 threads = 8 warps (warp tile 32x32),
// 2-stage cp.async double buffer.
// =========================================================================
#define PITCH 40
#define A_BYTES (128 * PITCH * 2)     // 10240
#define B_BYTES (64 * PITCH * 2)      // 5120
#define STAGE   (A_BYTES + B_BYTES)           // 15360
#define DSMEM   (2 * STAGE)                   // 30720

template<int MODE>
__global__ __launch_bounds__(256) void gemm_mma(
    const float* __restrict__ b1a, const float* __restrict__ bfa,
    const float* __restrict__ bb1, const float* __restrict__ bv1,
    const float* __restrict__ b1b, const float* __restrict__ bfb)
{
    extern __shared__ __align__(16) char dsm[];
    const uint32_t sbase = smem_u32(dsm);

    const int tid  = threadIdx.x;
    const int wid  = tid >> 5;
    const int lane = tid & 31;
    const int wm   = wid >> 1;          // 0..3 : m-quarter (32 rows)
    const int wn   = wid & 1;           // 0..1 : n-half (32 cols)
    const int nbase = blockIdx.x * 64;
    const int m0    = blockIdx.y * 128;

    const __half *A_p, *B_p;
    int lda, ldb, NC;
    if (MODE == 0) {
        A_p = g_Yh; lda = 512;
        B_p = g_WT0; ldb = 512; NC = 16;
    } else {
        A_p = (blockIdx.x == 4) ? g_HFh : g_H1h;
        lda = 256;
        B_p = g_WT1; ldb = 256; NC = 8;
    }

    const int ar0 = tid >> 2,  ak0 = (tid & 3) * 8;

    auto issue = [&](int c) {
        const uint32_t st = sbase + (c & 1) * STAGE;
        #pragma unroll
        for (int i = 0; i < 2; i++) {
            int row = ar0 + i * 64;
            uint32_t d = st + row * (PITCH*2) + ak0 * 2;
            const __half* sh = A_p + (size_t)(m0 + row) * lda + c * 32 + ak0;
            CP16(d, sh);
        }
        {
            int n  = ar0;
            uint32_t d = st + A_BYTES + n * (PITCH*2) + ak0 * 2;
            const __half* sh = B_p + (size_t)(nbase + n) * ldb + c * 32 + ak0;
            CP16(d, sh);
        }
        CP_COMMIT();
    };

    float acc[2][4][4];
    #pragma unroll
    for (int i = 0; i < 2; i++)
        #pragma unroll
        for (int j = 0; j < 4; j++)
            #pragma unroll
            for (int q = 0; q < 4; q++) acc[i][j][q] = 0.f;

    issue(0);

    const int g  = lane >> 3;
    const int li = lane & 7;

    for (int c = 0; c < NC; ++c) {
        if (c + 1 < NC) { issue(c + 1); CP_WAIT(1); }
        else            { CP_WAIT(0); }
        __syncthreads();

        const uint32_t st = sbase + (c & 1) * STAGE;
        const uint32_t sA = st;
        const uint32_t sB = st + A_BYTES;

        #pragma unroll
        for (int ks = 0; ks < 2; ks++) {
            const int am = wm * 32 + (g & 1) * 8 + li;
            const int ak = (g >> 1) * 8 + ks * 16;
            const int bn = wn * 32 + (g >> 1) * 8 + li;
            const int bk = (g & 1) * 8 + ks * 16;

            uint32_t ah[2][4], bh[4][2];
            #pragma unroll
            for (int mi = 0; mi < 2; mi++) {
                uint32_t a1 = sA + ((am + mi * 16) * PITCH + ak) * 2;
                LDSM4(ah[mi][0], ah[mi][1], ah[mi][2], ah[mi][3], a1);
            }
            #pragma unroll
            for (int bp = 0; bp < 2; bp++) {
                uint32_t a1 = sB + ((bn + bp * 16) * PITCH + bk) * 2;
                LDSM4(bh[2*bp][0], bh[2*bp][1], bh[2*bp+1][0], bh[2*bp+1][1], a1);
            }
            #pragma unroll
            for (int mi = 0; mi < 2; mi++)
                #pragma unroll
                for (int ni = 0; ni < 4; ni++)
                    MMA_F16(acc[mi][ni], ah[mi], bh[ni]);
        }
        __syncthreads();
    }

    // ---- epilogue ----
    #pragma unroll
    for (int mi = 0; mi < 2; mi++) {
        #pragma unroll
        for (int ni = 0; ni < 4; ni++) {
            int m  = m0 + wm * 32 + mi * 16 + (lane >> 2);
            int ng = nbase + wn * 32 + ni * 8 + 2 * (lane & 3);
            #pragma unroll
            for (int half = 0; half < 2; half++) {
                int mm = m + half * 8;
                float x0 = acc[mi][ni][half * 2 + 0];
                float x1 = acc[mi][ni][half * 2 + 1];
                if (MODE == 0) {
                    if (ng < 256) {
                        float2 b = *(const float2*)&b1a[ng];
                        float o0 = fmaxf(x0 + b.x, 0.f), o1 = fmaxf(x1 + b.y, 0.f);
                        *(__half2*)&g_H1h[(size_t)mm * 256 + ng] =
                            __halves2half2(__float2half_rn(o0), __float2half_rn(o1));
                    } else if (ng < 512) {
                        int nl = ng - 256;
                        float2 b = *(const float2*)&bfa[nl];
                        float o0 = fmaxf(x0 + b.x, 0.f), o1 = fmaxf(x1 + b.y, 0.f);
                        *(__half2*)&g_HFh[(size_t)mm * 256 + nl] =
                            __halves2half2(__float2half_rn(o0), __float2half_rn(o1));
                    } else if (ng < 544) {
                        int nl = ng - 512;
                        float2 b = *(const float2*)&bb1[nl];
                        float2 o = make_float2(x0 + b.x, x1 + b.y);
                        *(float2*)&g_B1[(size_t)mm * 32 + nl] = o;
                    } else {
                        int nl = ng - 544;
                        float2 b = *(const float2*)&bv1[nl];
                        float2 o = make_float2(fmaxf(x0 + b.x, 0.f), fmaxf(x1 + b.y, 0.f));
                        *(float2*)&g_Hv[(size_t)mm * 32 + nl] = o;
                    }
                } else {
                    if (nbase < 256) {
                        float2 b = *(const float2*)&b1b[ng];
                        float2 o = make_float2(fabsf(x0 + b.x), fabsf(x1 + b.y));
                        *(float2*)&g_W1[(size_t)mm * 256 + ng] = o;
                    } else {
                        int nl = ng - 256;
                        if (nl < 32) {
                            float2 b = *(const float2*)&bfb[nl];
                            float2 o = make_float2(fabsf(x0 + b.x), fabsf(x1 + b.y));
                            *(float2*)&g_WF[(size_t)mm * 32 + nl] = o;
                        }
                    }
                }
            }
        }
    }
}

// =========================================================================
// K4: final fused epilogue. One warp per row; lane = EMB index e.
// =========================================================================
__device__ __forceinline__ float wred(float v) {
    #pragma unroll
    for (int o = 16; o > 0; o >>= 1) v += __shfl_xor_sync(0xFFFFFFFFu, v, o);
    return v;
}

__global__ __launch_bounds__(256) void k4_final(
    const float* __restrict__ agent_qs,
    const float* __restrict__ Wv2, const float* __restrict__ bv2,
    float* __restrict__ out)
{
    const int w = threadIdx.x >> 5, lane = threadIdx.x & 31;
    const size_t r = (size_t)blockIdx.x * 8 + w;

    const float wv2v = Wv2[lane];

    float q[8];
    #pragma unroll
    for (int a = 0; a < 8; a++) q[a] = agent_qs[r * 8 + a];

    float w1r[8];
    const float* w1p = g_W1 + r * 256;
    #pragma unroll
    for (int a = 0; a < 8; a++) w1r[a] = w1p[a * 32 + lane];

    float x = g_B1[r * 32 + lane];
    #pragma unroll
    for (int a = 0; a < 8; a++) x += q[a] * w1r[a];
    const float h    = (x > 0.f) ? x : expm1f(x);
    const float delu = (h < 0.f) ? expf(h) : 1.f;

    const float wf = g_WF[r * 32 + lane];
    const float hv = g_Hv[r * 32 + lane];

    const float vsum = wred(hv * wv2v);
    const float qt   = wred(h * wf);
    if (lane == 0) out[r] = qt + vsum + bv2[0];

    const float t = delu * wf;
    float* gout = out + BTOT;
    #pragma unroll
    for (int a = 0; a < 8; a++) {
        float s = wred(w1r[a] * t);
        if (lane == a) gout[r * 8 + a] = s;
    }
}

// =========================================================================
extern "C" void kernel_launch(void* const* d_in, const int* in_sizes, int n_in,
                              void* d_out, int out_size)
{
    (void)in_sizes; (void)n_in; (void)out_size;
    const float* agent_qs = (const float*)d_in[0];
    const float* states = (const float*)d_in[2];   // d_in[1]=hist, d_in[3]=obs unused
    const float* W_tok  = (const float*)d_in[4];
    const float* b_tok  = (const float*)d_in[5];
    const float* W_yfc  = (const float*)d_in[6];
    const float* b_yfc  = (const float*)d_in[7];
    const float* W1a    = (const float*)d_in[8];
    const float* b1a    = (const float*)d_in[9];
    const float* W1b    = (const float*)d_in[10];
    const float* b1b    = (const float*)d_in[11];
    const float* Wfa    = (const float*)d_in[12];
    const float* bfa    = (const float*)d_in[13];
    const float* Wfb    = (const float*)d_in[14];
    const float* bfb    = (const float*)d_in[15];
    const float* Wb1    = (const float*)d_in[16];
    const float* bb1    = (const float*)d_in[17];
    const float* Wv1    = (const float*)d_in[18];
    const float* bv1    = (const float*)d_in[19];
    const float* Wv2    = (const float*)d_in[20];
    const float* bv2    = (const float*)d_in[21];
    float* out = (float*)d_out;

    cudaFuncSetAttribute(gemm_mma<0>, cudaFuncAttributeMaxDynamicSharedMemorySize, DSMEM);
    cudaFuncSetAttribute(gemm_mma<1>, cudaFuncAttributeMaxDynamicSharedMemorySize, DSMEM);
    cudaFuncSetAttribute(k1_mma, cudaFuncAttributeMaxDynamicSharedMemorySize, K1_SMEM);

    prep_split<<<1472, 256>>>(W1a, Wfa, Wb1, Wv1, W1b, Wfb);
    k1_mma<<<2048, 256, K1_SMEM>>>(states, W_tok, b_tok, W_yfc, b_yfc);
    gemm_mma<0><<<dim3(9, BTOT / 128), 256, DSMEM>>>(b1a, bfa, bb1, bv1, b1b, bfb);
    gemm_mma<1><<<dim3(5, BTOT / 128), 256, DSMEM>>>(b1a, bfa, bb1, bv1, b1b, bfb);
    k4_final<<<BTOT / 8, 256>>>(agent_qs, Wv2, bv2, out);
}

// round 12
// speedup vs baseline: 2.7599x; 1.0519x over previous
#include <cuda_runtime.h>
#include <cuda_fp16.h>
#include <cstdint>
#include <math.h>

// Problem constants
#define BTOT 32768      // BS*T = 128*256
#define SD   512        // STATE_DIM
#define EMB  32
#define HYP  256

// ---------------- global scratch (no allocations allowed) ----------------
__device__ __half g_Yh [(size_t)BTOT * SD];          // y (single fp16)
__device__ __half g_H1h[(size_t)BTOT * HYP];         // H1 (single fp16)
__device__ __half g_HFh[(size_t)BTOT * HYP];         // HF (single fp16)
__device__ __half g_W1[(size_t)BTOT * 256];          // abs(H1@W1b+b1b)  fp16
__device__ float g_B1[(size_t)BTOT * EMB];           // y@Wb1+bb1
__device__ float g_Hv[(size_t)BTOT * EMB];           // relu(y@Wv1+bv1)
__device__ float g_WF[(size_t)BTOT * EMB];           // abs(HF@Wfb+bfb)

// transposed weights: [n][k] single fp16
__device__ __half g_WT0[576 * 512];                  // [W1a|Wfa|Wb1|Wv1]^T
__device__ __half g_WT1[320 * 256];                  // [W1b|Wfb|pad]^T

__device__ __forceinline__ uint32_t smem_u32(const void* p) {
    return (uint32_t)__cvta_generic_to_shared(p);
}

#define LDSM4(r0, r1, r2, r3, addr) \
    asm volatile("ldmatrix.sync.aligned.m8n8.x4.shared.b16 {%0,%1,%2,%3}, [%4];" \
        : "=r"(r0), "=r"(r1), "=r"(r2), "=r"(r3) : "r"(addr))

#define MMA_F16(c, a, b) \
    asm volatile("mma.sync.aligned.m16n8k16.row.col.f32.f16.f16.f32 " \
        "{%0,%1,%2,%3}, {%4,%5,%6,%7}, {%8,%9}, {%0,%1,%2,%3};" \
        : "+f"((c)[0]), "+f"((c)[1]), "+f"((c)[2]), "+f"((c)[3]) \
        : "r"((a)[0]), "r"((a)[1]), "r"((a)[2]), "r"((a)[3]), \
          "r"((b)[0]), "r"((b)[1]))

#define CP16(dst, src) \
    asm volatile("cp.async.cg.shared.global [%0], [%1], 16;" :: "r"(dst), "l"(src))
#define CP_COMMIT() asm volatile("cp.async.commit_group;" ::: "memory")
#define CP_WAIT(n)  asm volatile("cp.async.wait_group %0;" :: "n"(n) : "memory")

__device__ __forceinline__ void h_split(float v, __half& h, __half& l) {
    h = __float2half_rn(v);
    l = __float2half_rn(v - __half2float(h));
}

// =========================================================================
// prep: transpose all GEMM weights to fp16 [n][k] (once per launch, tiny)
// =========================================================================
__global__ __launch_bounds__(256) void prep_split(
    const float* __restrict__ W1a, const float* __restrict__ Wfa,
    const float* __restrict__ Wb1, const float* __restrict__ Wv1,
    const float* __restrict__ W1b, const float* __restrict__ Wfb)
{
    int idx = blockIdx.x * 256 + threadIdx.x;
    if (idx < 576 * 512) {
        int n = idx >> 9, k = idx & 511;
        float v;
        if (n < 256)      v = W1a[k * 256 + n];
        else if (n < 512) v = Wfa[k * 256 + (n - 256)];
        else if (n < 544) v = Wb1[k * 32 + (n - 512)];
        else              v = Wv1[k * 32 + (n - 544)];
        g_WT0[idx] = __float2half_rn(v);
    }
    int idx2 = idx - 576 * 512;
    if (idx2 >= 0 && idx2 < 320 * 256) {
        int n = idx2 >> 8, k = idx2 & 255;
        float v = 0.f;
        if (n < 256)      v = W1b[k * 256 + n];
        else if (n < 288) v = Wfb[k * 32 + (n - 256)];
        g_WT1[idx2] = __float2half_rn(v);
    }
}

// =========================================================================
// k1_mma: token embed on tensor cores (fp16, A split hi/lo, B single).
// stage1: E = relu(A @ W_tok + b_tok)   (K=64, N=32)
// stage2: Y = relu(E @ W_yfc + b_yfc)   (K=32, N=64) -> g_Yh (single fp16)
// 128 rows/CTA, 8 warps, each warp owns 16 rows.
// =========================================================================
#define P_A 72
#define P_E 40

#define K1_sAh  0
#define K1_sAl  (K1_sAh + 128 * P_A * 2)      // 18432
#define K1_sBh  (K1_sAl + 128 * P_A * 2)      // 36864 (Wtok^T [32][72])
#define K1_sEh  (K1_sBh + 32 * P_A * 2)       // 41472 (E hi [128][40])
#define K1_sEl  (K1_sEh + 128 * P_E * 2)      // 51712
#define K1_sCh  (K1_sEl + 128 * P_E * 2)      // 61952 (Wyfc^T [64][40])
#define K1_SMEM (K1_sCh + 64 * P_E * 2)       // 67072

__global__ __launch_bounds__(256, 2) void k1_mma(
    const float* __restrict__ states,
    const float* __restrict__ Wt, const float* __restrict__ bt,
    const float* __restrict__ Wy, const float* __restrict__ by)
{
    extern __shared__ __align__(16) char dsm[];
    const uint32_t sb = smem_u32(dsm);
    const int tid  = threadIdx.x;
    const int w    = tid >> 5;
    const int lane = tid & 31;
    const int g    = lane >> 3;
    const int li   = lane & 7;

    // ---- stage inputs: split A, round weights ----
    {
        const float4* S4 = (const float4*)(states + (size_t)blockIdx.x * 128 * 64);
        __half* Ah = (__half*)(dsm + K1_sAh);
        __half* Al = (__half*)(dsm + K1_sAl);
        #pragma unroll
        for (int i = 0; i < 8; i++) {
            int idx = tid + i * 256;
            int row = idx >> 4;
            int k4  = (idx & 15) * 4;
            float4 v = S4[idx];
            int e = row * P_A + k4;
            __half h0,l0,h1,l1,h2,l2,h3,l3;
            h_split(v.x,h0,l0); h_split(v.y,h1,l1);
            h_split(v.z,h2,l2); h_split(v.w,h3,l3);
            *(__half2*)&Ah[e]   = __halves2half2(h0,h1);
            *(__half2*)&Ah[e+2] = __halves2half2(h2,h3);
            *(__half2*)&Al[e]   = __halves2half2(l0,l1);
            *(__half2*)&Al[e+2] = __halves2half2(l2,l3);
        }
        __half* Bh = (__half*)(dsm + K1_sBh);
        #pragma unroll
        for (int i = 0; i < 8; i++) {
            int idx = tid + i * 256;
            int n = idx & 31, k = idx >> 5;
            Bh[n * P_A + k] = __float2half_rn(Wt[k * 32 + n]);
        }
        __half* Ch = (__half*)(dsm + K1_sCh);
        #pragma unroll
        for (int i = 0; i < 8; i++) {
            int idx = tid + i * 256;
            int n = idx & 63, k = idx >> 6;
            Ch[n * P_E + k] = __float2half_rn(Wy[k * 64 + n]);
        }
    }
    __syncthreads();

    // ---- stage1: E = relu(A @ Wtok + bt) ----
    {
        float acc[4][4];
        #pragma unroll
        for (int i = 0; i < 4; i++)
            #pragma unroll
            for (int q = 0; q < 4; q++) acc[i][q] = 0.f;

        #pragma unroll
        for (int ks = 0; ks < 4; ks++) {
            const int am = w * 16 + (g & 1) * 8 + li;
            const int ak = (g >> 1) * 8 + ks * 16;
            const int bn = (g >> 1) * 8 + li;
            const int bk = (g & 1) * 8 + ks * 16;
            uint32_t ah[4], al[4], bh[4][2];
            LDSM4(ah[0],ah[1],ah[2],ah[3], sb + K1_sAh + (am * P_A + ak) * 2);
            LDSM4(al[0],al[1],al[2],al[3], sb + K1_sAl + (am * P_A + ak) * 2);
            #pragma unroll
            for (int bp = 0; bp < 2; bp++) {
                LDSM4(bh[2*bp][0], bh[2*bp][1], bh[2*bp+1][0], bh[2*bp+1][1],
                      sb + K1_sBh + ((bn + bp * 16) * P_A + bk) * 2);
            }
            #pragma unroll
            for (int ni = 0; ni < 4; ni++) {
                MMA_F16(acc[ni], ah, bh[ni]);
                MMA_F16(acc[ni], al, bh[ni]);
            }
        }
        __half* Eh = (__half*)(dsm + K1_sEh);
        __half* El = (__half*)(dsm + K1_sEl);
        #pragma unroll
        for (int ni = 0; ni < 4; ni++) {
            int n = ni * 8 + 2 * (lane & 3);
            float b0 = bt[n], b1 = bt[n + 1];
            #pragma unroll
            for (int half = 0; half < 2; half++) {
                int m = w * 16 + (lane >> 2) + half * 8;
                float o0 = fmaxf(acc[ni][half*2+0] + b0, 0.f);
                float o1 = fmaxf(acc[ni][half*2+1] + b1, 0.f);
                __half h0,l0,h1,l1;
                h_split(o0,h0,l0); h_split(o1,h1,l1);
                *(__half2*)&Eh[m * P_E + n] = __halves2half2(h0,h1);
                *(__half2*)&El[m * P_E + n] = __halves2half2(l0,l1);
            }
        }
    }
    __syncthreads();

    // ---- stage2: Y = relu(E @ Wyfc + by), N=64 -> single fp16 ----
    {
        float acc[8][4];
        #pragma unroll
        for (int i = 0; i < 8; i++)
            #pragma unroll
            for (int q = 0; q < 4; q++) acc[i][q] = 0.f;

        #pragma unroll
        for (int ks = 0; ks < 2; ks++) {
            const int am = w * 16 + (g & 1) * 8 + li;
            const int ak = (g >> 1) * 8 + ks * 16;
            const int bn = (g >> 1) * 8 + li;
            const int bk = (g & 1) * 8 + ks * 16;
            uint32_t ah[4], al[4], bh[8][2];
            LDSM4(ah[0],ah[1],ah[2],ah[3], sb + K1_sEh + (am * P_E + ak) * 2);
            LDSM4(al[0],al[1],al[2],al[3], sb + K1_sEl + (am * P_E + ak) * 2);
            #pragma unroll
            for (int bp = 0; bp < 4; bp++) {
                LDSM4(bh[2*bp][0], bh[2*bp][1], bh[2*bp+1][0], bh[2*bp+1][1],
                      sb + K1_sCh + ((bn + bp * 16) * P_E + bk) * 2);
            }
            #pragma unroll
            for (int ni = 0; ni < 8; ni++) {
                MMA_F16(acc[ni], ah, bh[ni]);
                MMA_F16(acc[ni], al, bh[ni]);
            }
        }
        #pragma unroll
        for (int ni = 0; ni < 8; ni++) {
            int n = ni * 8 + 2 * (lane & 3);
            float b0 = by[n], b1 = by[n + 1];
            #pragma unroll
            for (int half = 0; half < 2; half++) {
                int m = w * 16 + (lane >> 2) + half * 8;
                size_t R = (size_t)blockIdx.x * 128 + m;
                float o0 = fmaxf(acc[ni][half*2+0] + b0, 0.f);
                float o1 = fmaxf(acc[ni][half*2+1] + b1, 0.f);
                *(__half2*)&g_Yh[R * 64 + n] =
                    __halves2half2(__float2half_rn(o0), __float2half_rn(o1));
            }
        }
    }
}

// =========================================================================
// gemm_mma<MODE>: fp16 mma.sync, single-product (A fp16, B fp16).
// MODE 0: C(B,576) = Y @ WT0 -> H1 | HF | B1 | Hv
// MODE 1: blocks 0-3: W1 = abs(H1@W1b+b1b); block 4: WF = abs(HF@Wfb+bfb)
// BM=128, BN=64, BK=32, 256 threads = 8 warps (warp tile 32x32).
// 4-stage cp.async ring, prefetch distance 3, ONE __syncthreads per chunk.
// =========================================================================
#define PITCH 40
#define A_BYTES (128 * PITCH * 2)     // 10240
#define B_BYTES (64 * PITCH * 2)      // 5120
#define STAGE   (A_BYTES + B_BYTES)           // 15360
#define NSTAGE  4
#define DSMEM   (NSTAGE * STAGE)              // 61440

template<int MODE>
__global__ __launch_bounds__(256) void gemm_mma(
    const float* __restrict__ b1a, const float* __restrict__ bfa,
    const float* __restrict__ bb1, const float* __restrict__ bv1,
    const float* __restrict__ b1b, const float* __restrict__ bfb)
{
    extern __shared__ __align__(16) char dsm[];
    const uint32_t sbase = smem_u32(dsm);

    const int tid  = threadIdx.x;
    const int wid  = tid >> 5;
    const int lane = tid & 31;
    const int wm   = wid >> 1;          // 0..3 : m-quarter (32 rows)
    const int wn   = wid & 1;           // 0..1 : n-half (32 cols)
    const int nbase = blockIdx.x * 64;
    const int m0    = blockIdx.y * 128;

    const __half *A_p, *B_p;
    int lda, ldb, NC;
    if (MODE == 0) {
        A_p = g_Yh; lda = 512;
        B_p = g_WT0; ldb = 512; NC = 16;
    } else {
        A_p = (blockIdx.x == 4) ? g_HFh : g_H1h;
        lda = 256;
        B_p = g_WT1; ldb = 256; NC = 8;
    }

    const int ar0 = tid >> 2,  ak0 = (tid & 3) * 8;

    auto issue = [&](int c) {
        const uint32_t st = sbase + (c & (NSTAGE - 1)) * STAGE;
        #pragma unroll
        for (int i = 0; i < 2; i++) {
            int row = ar0 + i * 64;
            uint32_t d = st + row * (PITCH*2) + ak0 * 2;
            const __half* sh = A_p + (size_t)(m0 + row) * lda + c * 32 + ak0;
            CP16(d, sh);
        }
        {
            int n  = ar0;
            uint32_t d = st + A_BYTES + n * (PITCH*2) + ak0 * 2;
            const __half* sh = B_p + (size_t)(nbase + n) * ldb + c * 32 + ak0;
            CP16(d, sh);
        }
        CP_COMMIT();
    };

    float acc[2][4][4];
    #pragma unroll
    for (int i = 0; i < 2; i++)
        #pragma unroll
        for (int j = 0; j < 4; j++)
            #pragma unroll
            for (int q = 0; q < 4; q++) acc[i][j][q] = 0.f;

    issue(0); issue(1); issue(2);

    const int g  = lane >> 3;
    const int li = lane & 7;

    for (int c = 0; c < NC; ++c) {
        {
            int rem = NC - 1 - c;          // groups younger than c still issued
            if (rem >= 2)      CP_WAIT(2);
            else if (rem == 1) CP_WAIT(1);
            else               CP_WAIT(0);
        }
        __syncthreads();                   // chunk c visible; chunk c-1 consumed by ALL warps
        if (c + 3 < NC) issue(c + 3);      // safe: stage (c+3)%4 held chunk c-1

        const uint32_t st = sbase + (c & (NSTAGE - 1)) * STAGE;
        const uint32_t sA = st;
        const uint32_t sB = st + A_BYTES;

        #pragma unroll
        for (int ks = 0; ks < 2; ks++) {
            const int am = wm * 32 + (g & 1) * 8 + li;
            const int ak = (g >> 1) * 8 + ks * 16;
            const int bn = wn * 32 + (g >> 1) * 8 + li;
            const int bk = (g & 1) * 8 + ks * 16;

            uint32_t ah[2][4], bh[4][2];
            #pragma unroll
            for (int mi = 0; mi < 2; mi++) {
                uint32_t a1 = sA + ((am + mi * 16) * PITCH + ak) * 2;
                LDSM4(ah[mi][0], ah[mi][1], ah[mi][2], ah[mi][3], a1);
            }
            #pragma unroll
            for (int bp = 0; bp < 2; bp++) {
                uint32_t a1 = sB + ((bn + bp * 16) * PITCH + bk) * 2;
                LDSM4(bh[2*bp][0], bh[2*bp][1], bh[2*bp+1][0], bh[2*bp+1][1], a1);
            }
            #pragma unroll
            for (int mi = 0; mi < 2; mi++)
                #pragma unroll
                for (int ni = 0; ni < 4; ni++)
                    MMA_F16(acc[mi][ni], ah[mi], bh[ni]);
        }
    }

    // ---- epilogue ----
    #pragma unroll
    for (int mi = 0; mi < 2; mi++) {
        #pragma unroll
        for (int ni = 0; ni < 4; ni++) {
            int m  = m0 + wm * 32 + mi * 16 + (lane >> 2);
            int ng = nbase + wn * 32 + ni * 8 + 2 * (lane & 3);
            #pragma unroll
            for (int half = 0; half < 2; half++) {
                int mm = m + half * 8;
                float x0 = acc[mi][ni][half * 2 + 0];
                float x1 = acc[mi][ni][half * 2 + 1];
                if (MODE == 0) {
                    if (ng < 256) {
                        float2 b = *(const float2*)&b1a[ng];
                        float o0 = fmaxf(x0 + b.x, 0.f), o1 = fmaxf(x1 + b.y, 0.f);
                        *(__half2*)&g_H1h[(size_t)mm * 256 + ng] =
                            __halves2half2(__float2half_rn(o0), __float2half_rn(o1));
                    } else if (ng < 512) {
                        int nl = ng - 256;
                        float2 b = *(const float2*)&bfa[nl];
                        float o0 = fmaxf(x0 + b.x, 0.f), o1 = fmaxf(x1 + b.y, 0.f);
                        *(__half2*)&g_HFh[(size_t)mm * 256 + nl] =
                            __halves2half2(__float2half_rn(o0), __float2half_rn(o1));
                    } else if (ng < 544) {
                        int nl = ng - 512;
                        float2 b = *(const float2*)&bb1[nl];
                        float2 o = make_float2(x0 + b.x, x1 + b.y);
                        *(float2*)&g_B1[(size_t)mm * 32 + nl] = o;
                    } else {
                        int nl = ng - 544;
                        float2 b = *(const float2*)&bv1[nl];
                        float2 o = make_float2(fmaxf(x0 + b.x, 0.f), fmaxf(x1 + b.y, 0.f));
                        *(float2*)&g_Hv[(size_t)mm * 32 + nl] = o;
                    }
                } else {
                    if (nbase < 256) {
                        float2 b = *(const float2*)&b1b[ng];
                        float o0 = fabsf(x0 + b.x), o1 = fabsf(x1 + b.y);
                        *(__half2*)&g_W1[(size_t)mm * 256 + ng] =
                            __halves2half2(__float2half_rn(o0), __float2half_rn(o1));
                    } else {
                        int nl = ng - 256;
                        if (nl < 32) {
                            float2 b = *(const float2*)&bfb[nl];
                            float2 o = make_float2(fabsf(x0 + b.x), fabsf(x1 + b.y));
                            *(float2*)&g_WF[(size_t)mm * 32 + nl] = o;
                        }
                    }
                }
            }
        }
    }
}

// =========================================================================
// K4: final fused epilogue. One warp per row; lane = EMB index e.
// =========================================================================
__device__ __forceinline__ float wred(float v) {
    #pragma unroll
    for (int o = 16; o > 0; o >>= 1) v += __shfl_xor_sync(0xFFFFFFFFu, v, o);
    return v;
}

__global__ __launch_bounds__(256) void k4_final(
    const float* __restrict__ agent_qs,
    const float* __restrict__ Wv2, const float* __restrict__ bv2,
    float* __restrict__ out)
{
    const int w = threadIdx.x >> 5, lane = threadIdx.x & 31;
    const size_t r = (size_t)blockIdx.x * 8 + w;

    const float wv2v = Wv2[lane];

    float q[8];
    #pragma unroll
    for (int a = 0; a < 8; a++) q[a] = agent_qs[r * 8 + a];

    float w1r[8];
    const __half* w1p = g_W1 + r * 256;
    #pragma unroll
    for (int a = 0; a < 8; a++) w1r[a] = __half2float(w1p[a * 32 + lane]);

    float x = g_B1[r * 32 + lane];
    #pragma unroll
    for (int a = 0; a < 8; a++) x += q[a] * w1r[a];
    const float h    = (x > 0.f) ? x : expm1f(x);
    const float delu = (h < 0.f) ? expf(h) : 1.f;

    const float wf = g_WF[r * 32 + lane];
    const float hv = g_Hv[r * 32 + lane];

    const float vsum = wred(hv * wv2v);
    const float qt   = wred(h * wf);
    if (lane == 0) out[r] = qt + vsum + bv2[0];

    const float t = delu * wf;
    float* gout = out + BTOT;
    #pragma unroll
    for (int a = 0; a < 8; a++) {
        float s = wred(w1r[a] * t);
        if (lane == a) gout[r * 8 + a] = s;
    }
}

// =========================================================================
extern "C" void kernel_launch(void* const* d_in, const int* in_sizes, int n_in,
                              void* d_out, int out_size)
{
    (void)in_sizes; (void)n_in; (void)out_size;
    const float* agent_qs = (const float*)d_in[0];
    const float* states = (const float*)d_in[2];   // d_in[1]=hist, d_in[3]=obs unused
    const float* W_tok  = (const float*)d_in[4];
    const float* b_tok  = (const float*)d_in[5];
    const float* W_yfc  = (const float*)d_in[6];
    const float* b_yfc  = (const float*)d_in[7];
    const float* W1a    = (const float*)d_in[8];
    const float* b1a    = (const float*)d_in[9];
    const float* W1b    = (const float*)d_in[10];
    const float* b1b    = (const float*)d_in[11];
    const float* Wfa    = (const float*)d_in[12];
    const float* bfa    = (const float*)d_in[13];
    const float* Wfb    = (const float*)d_in[14];
    const float* bfb    = (const float*)d_in[15];
    const float* Wb1    = (const float*)d_in[16];
    const float* bb1    = (const float*)d_in[17];
    const float* Wv1    = (const float*)d_in[18];
    const float* bv1    = (const float*)d_in[19];
    const float* Wv2    = (const float*)d_in[20];
    const float* bv2    = (const float*)d_in[21];
    float* out = (float*)d_out;

    cudaFuncSetAttribute(gemm_mma<0>, cudaFuncAttributeMaxDynamicSharedMemorySize, DSMEM);
    cudaFuncSetAttribute(gemm_mma<1>, cudaFuncAttributeMaxDynamicSharedMemorySize, DSMEM);
    cudaFuncSetAttribute(k1_mma, cudaFuncAttributeMaxDynamicSharedMemorySize, K1_SMEM);

    prep_split<<<1472, 256>>>(W1a, Wfa, Wb1, Wv1, W1b, Wfb);
    k1_mma<<<2048, 256, K1_SMEM>>>(states, W_tok, b_tok, W_yfc, b_yfc);
    gemm_mma<0><<<dim3(9, BTOT / 128), 256, DSMEM>>>(b1a, bfa, bb1, bv1, b1b, bfb);
    gemm_mma<1><<<dim3(5, BTOT / 128), 256, DSMEM>>>(b1a, bfa, bb1, bv1, b1b, bfb);
    k4_final<<<BTOT / 8, 256>>>(agent_qs, Wv2, bv2, out);
}